// round 14
// baseline (speedup 1.0000x reference)
#include <cuda_runtime.h>
#include <cuda_bf16.h>
#include <cuda_fp16.h>
#include <stdint.h>

#define Lq     2048
#define EMB    1024
#define NHEAD  16
#define HD     64
#define NT     (Lq / 64)                       // key tiles
#define MP_WORDS (NHEAD * Lq * (Lq / 32))      // packed mask words

// Scratch (allocation-free rule: device globals)
__device__ float    g_Q[Lq * EMB];
__device__ __half   g_Kh[Lq * EMB];            // K projection, fp16
__device__ __half   g_Vh[Lq * EMB];            // V projection, fp16 hi
__device__ __half   g_Vl[Lq * EMB];            // V projection, fp16 lo
__device__ float    g_A[Lq * EMB];
__device__ uint32_t g_Mp[MP_WORDS];            // bit-packed mask (8 MB)

__device__ __forceinline__ uint32_t smem_u32(const void* p) {
    uint32_t a;
    asm("{ .reg .u64 t; cvta.to.shared.u64 t, %1; cvt.u32.u64 %0, t; }" : "=r"(a) : "l"(p));
    return a;
}
__device__ __forceinline__ uint32_t cvt2bf(float x0, float x1) {
    uint32_t r;
    asm("cvt.rn.bf16x2.f32 %0, %1, %2;" : "=r"(r) : "f"(x1), "f"(x0));
    return r;
}
__device__ __forceinline__ float bf_lowf(uint32_t h)  { return __uint_as_float(h << 16); }
__device__ __forceinline__ float bf_highf(uint32_t h) { return __uint_as_float(h & 0xffff0000u); }

__device__ __forceinline__ uint32_t cvt2h(float x0, float x1) {
    __half2 h = __floats2half2_rn(x0, x1);
    return *reinterpret_cast<uint32_t*>(&h);
}
__device__ __forceinline__ float h_lowf(uint32_t h) {
    __half2 hh = *reinterpret_cast<__half2*>(&h);
    return __low2float(hh);
}
__device__ __forceinline__ float h_highf(uint32_t h) {
    __half2 hh = *reinterpret_cast<__half2*>(&h);
    return __high2float(hh);
}

// m16n8k16 bf16 HMMA (GEMM path)
__device__ __forceinline__ void mma_bf16(float d[4], const uint32_t a[4],
                                         const uint32_t b0, const uint32_t b1) {
    asm volatile(
        "mma.sync.aligned.m16n8k16.row.col.f32.bf16.bf16.f32 "
        "{%0,%1,%2,%3}, {%4,%5,%6,%7}, {%8,%9}, {%0,%1,%2,%3};\n"
        : "+f"(d[0]), "+f"(d[1]), "+f"(d[2]), "+f"(d[3])
        : "r"(a[0]), "r"(a[1]), "r"(a[2]), "r"(a[3]), "r"(b0), "r"(b1));
}
// m16n8k16 fp16 HMMA (attention path)
__device__ __forceinline__ void mma_f16(float d[4], const uint32_t a[4],
                                        const uint32_t b0, const uint32_t b1) {
    asm volatile(
        "mma.sync.aligned.m16n8k16.row.col.f32.f16.f16.f32 "
        "{%0,%1,%2,%3}, {%4,%5,%6,%7}, {%8,%9}, {%0,%1,%2,%3};\n"
        : "+f"(d[0]), "+f"(d[1]), "+f"(d[2]), "+f"(d[3])
        : "r"(a[0]), "r"(a[1]), "r"(a[2]), "r"(a[3]), "r"(b0), "r"(b1));
}

__device__ __forceinline__ void ldsm4(uint32_t r[4], uint32_t addr) {
    asm volatile("ldmatrix.sync.aligned.m8n8.x4.shared.b16 {%0,%1,%2,%3}, [%4];"
                 : "=r"(r[0]), "=r"(r[1]), "=r"(r[2]), "=r"(r[3]) : "r"(addr));
}
__device__ __forceinline__ void ldsm4t(uint32_t r[4], uint32_t addr) {
    asm volatile("ldmatrix.sync.aligned.m8n8.x4.trans.shared.b16 {%0,%1,%2,%3}, [%4];"
                 : "=r"(r[0]), "=r"(r[1]), "=r"(r[2]), "=r"(r[3]) : "r"(addr));
}

// ===========================================================================
// bf16 3xsplit NT GEMM body (validated R9-R13). BK=32.
// CTA tile 64x128, 8 warps (2m x 4n), warp 32x32.
// MODE 0: fp32 C.  MODE 1: fp16 C (Ch).  MODE 2: fp16 hi/lo C (Ch, Cl).
// ===========================================================================
template<int MODE>
__device__ __forceinline__ void gemm_body(const float* __restrict__ A,
                                          const float* __restrict__ B,
                                          float* __restrict__ C,
                                          __half* __restrict__ Ch,
                                          __half* __restrict__ Cl,
                                          int bm, int bn)
{
    __shared__ uint32_t Ah[64][20],  Al[64][20];    // 64 rows x 80B
    __shared__ uint32_t Bh[128][20], Bl[128][20];   // 128 rows x 80B

    const int tid  = threadIdx.x;
    const int lane = tid & 31;
    const int wid  = tid >> 5;
    const int g    = lane >> 2;
    const int t4   = lane & 3;
    const int wm   = (wid & 1) * 32;
    const int wn   = (wid >> 1) * 32;

    const int ar = tid >> 2, aw = tid & 3;
    const int br = tid >> 1, bw = tid & 1;
    const float* ap = A + (size_t)(bm + ar) * EMB + aw * 4;
    const float* bp = B + (size_t)(bn + br) * EMB + bw * 16;

    const uint32_t sAh = smem_u32(Ah), sAl = smem_u32(Al);
    const uint32_t sBh = smem_u32(Bh), sBl = smem_u32(Bl);
    const int arow = lane & 15, akoff = (lane >> 4) * 16;
    const int brow = (lane & 7) + ((lane >> 4) << 3);
    const int bkoff = ((lane >> 3) & 1) * 16;
    uint32_t aAh[2], aAl[2], aBh[2], aBl[2];
    #pragma unroll
    for (int mi = 0; mi < 2; ++mi) {
        aAh[mi] = sAh + (wm + 16 * mi + arow) * 80 + akoff;
        aAl[mi] = sAl + (wm + 16 * mi + arow) * 80 + akoff;
    }
    #pragma unroll
    for (int p = 0; p < 2; ++p) {
        aBh[p] = sBh + (wn + 16 * p + brow) * 80 + bkoff;
        aBl[p] = sBl + (wn + 16 * p + brow) * 80 + bkoff;
    }

    float d[2][4][4];
    #pragma unroll
    for (int i = 0; i < 2; ++i)
        #pragma unroll
        for (int j = 0; j < 4; ++j)
            #pragma unroll
            for (int r = 0; r < 4; ++r) d[i][j][r] = 0.f;

    float4 pa0 = *(const float4*)(ap);
    float4 pa1 = *(const float4*)(ap + 16);
    float4 pb0 = *(const float4*)(bp);
    float4 pb1 = *(const float4*)(bp + 4);
    float4 pb2 = *(const float4*)(bp + 8);
    float4 pb3 = *(const float4*)(bp + 12);

    #pragma unroll 1
    for (int c = 0; c < EMB / 32; ++c) {
        __syncthreads();
        {
            uint32_t h0 = cvt2bf(pa0.x, pa0.y), h1 = cvt2bf(pa0.z, pa0.w);
            uint32_t l0 = cvt2bf(pa0.x - bf_lowf(h0), pa0.y - bf_highf(h0));
            uint32_t l1 = cvt2bf(pa0.z - bf_lowf(h1), pa0.w - bf_highf(h1));
            *(uint2*)&Ah[ar][aw * 2] = make_uint2(h0, h1);
            *(uint2*)&Al[ar][aw * 2] = make_uint2(l0, l1);
            h0 = cvt2bf(pa1.x, pa1.y); h1 = cvt2bf(pa1.z, pa1.w);
            l0 = cvt2bf(pa1.x - bf_lowf(h0), pa1.y - bf_highf(h0));
            l1 = cvt2bf(pa1.z - bf_lowf(h1), pa1.w - bf_highf(h1));
            *(uint2*)&Ah[ar][aw * 2 + 8] = make_uint2(h0, h1);
            *(uint2*)&Al[ar][aw * 2 + 8] = make_uint2(l0, l1);

            uint32_t bh0 = cvt2bf(pb0.x, pb0.y), bh1 = cvt2bf(pb0.z, pb0.w);
            uint32_t bh2 = cvt2bf(pb1.x, pb1.y), bh3 = cvt2bf(pb1.z, pb1.w);
            uint32_t bh4 = cvt2bf(pb2.x, pb2.y), bh5 = cvt2bf(pb2.z, pb2.w);
            uint32_t bh6 = cvt2bf(pb3.x, pb3.y), bh7 = cvt2bf(pb3.z, pb3.w);
            uint32_t bl0 = cvt2bf(pb0.x - bf_lowf(bh0), pb0.y - bf_highf(bh0));
            uint32_t bl1 = cvt2bf(pb0.z - bf_lowf(bh1), pb0.w - bf_highf(bh1));
            uint32_t bl2 = cvt2bf(pb1.x - bf_lowf(bh2), pb1.y - bf_highf(bh2));
            uint32_t bl3 = cvt2bf(pb1.z - bf_lowf(bh3), pb1.w - bf_highf(bh3));
            uint32_t bl4 = cvt2bf(pb2.x - bf_lowf(bh4), pb2.y - bf_highf(bh4));
            uint32_t bl5 = cvt2bf(pb2.z - bf_lowf(bh5), pb2.w - bf_highf(bh5));
            uint32_t bl6 = cvt2bf(pb3.x - bf_lowf(bh6), pb3.y - bf_highf(bh6));
            uint32_t bl7 = cvt2bf(pb3.z - bf_lowf(bh7), pb3.w - bf_highf(bh7));
            *(uint4*)&Bh[br][bw * 8]     = make_uint4(bh0, bh1, bh2, bh3);
            *(uint4*)&Bh[br][bw * 8 + 4] = make_uint4(bh4, bh5, bh6, bh7);
            *(uint4*)&Bl[br][bw * 8]     = make_uint4(bl0, bl1, bl2, bl3);
            *(uint4*)&Bl[br][bw * 8 + 4] = make_uint4(bl4, bl5, bl6, bl7);
        }
        if (c + 1 < EMB / 32) {
            pa0 = *(const float4*)(ap + (c + 1) * 32);
            pa1 = *(const float4*)(ap + (c + 1) * 32 + 16);
            pb0 = *(const float4*)(bp + (c + 1) * 32);
            pb1 = *(const float4*)(bp + (c + 1) * 32 + 4);
            pb2 = *(const float4*)(bp + (c + 1) * 32 + 8);
            pb3 = *(const float4*)(bp + (c + 1) * 32 + 12);
        }
        __syncthreads();

        #pragma unroll
        for (int kk = 0; kk < 2; ++kk) {
            uint32_t fah[2][4], fal[2][4], fbh[2][4], fbl[2][4];
            #pragma unroll
            for (int mi = 0; mi < 2; ++mi) {
                ldsm4(fah[mi], aAh[mi] + kk * 32);
                ldsm4(fal[mi], aAl[mi] + kk * 32);
            }
            #pragma unroll
            for (int p = 0; p < 2; ++p) {
                ldsm4(fbh[p], aBh[p] + kk * 32);
                ldsm4(fbl[p], aBl[p] + kk * 32);
            }
            #pragma unroll
            for (int mi = 0; mi < 2; ++mi) {
                #pragma unroll
                for (int ni = 0; ni < 4; ++ni) {
                    const int p = ni >> 1, q = (ni & 1) * 2;
                    uint32_t b0h = fbh[p][q], b1h = fbh[p][q + 1];
                    uint32_t b0l = fbl[p][q], b1l = fbl[p][q + 1];
                    mma_bf16(d[mi][ni], fah[mi], b0h, b1h);
                    mma_bf16(d[mi][ni], fah[mi], b0l, b1l);
                    mma_bf16(d[mi][ni], fal[mi], b0h, b1h);
                }
            }
        }
    }

    #pragma unroll
    for (int mi = 0; mi < 2; ++mi) {
        int m = bm + wm + mi * 16 + g;
        #pragma unroll
        for (int ni = 0; ni < 4; ++ni) {
            int n = bn + wn + ni * 8 + 2 * t4;
            if (MODE == 0) {
                *(float2*)(C + (size_t)m * EMB + n) =
                    make_float2(d[mi][ni][0], d[mi][ni][1]);
                *(float2*)(C + (size_t)(m + 8) * EMB + n) =
                    make_float2(d[mi][ni][2], d[mi][ni][3]);
            } else if (MODE == 1) {
                *(uint32_t*)(Ch + (size_t)m * EMB + n) =
                    cvt2h(d[mi][ni][0], d[mi][ni][1]);
                *(uint32_t*)(Ch + (size_t)(m + 8) * EMB + n) =
                    cvt2h(d[mi][ni][2], d[mi][ni][3]);
            } else {
                uint32_t vh0 = cvt2h(d[mi][ni][0], d[mi][ni][1]);
                uint32_t vl0 = cvt2h(d[mi][ni][0] - h_lowf(vh0),
                                     d[mi][ni][1] - h_highf(vh0));
                uint32_t vh1 = cvt2h(d[mi][ni][2], d[mi][ni][3]);
                uint32_t vl1 = cvt2h(d[mi][ni][2] - h_lowf(vh1),
                                     d[mi][ni][3] - h_highf(vh1));
                *(uint32_t*)(Ch + (size_t)m * EMB + n)       = vh0;
                *(uint32_t*)(Cl + (size_t)m * EMB + n)       = vl0;
                *(uint32_t*)(Ch + (size_t)(m + 8) * EMB + n) = vh1;
                *(uint32_t*)(Cl + (size_t)(m + 8) * EMB + n) = vl1;
            }
        }
    }
}

// fused QKV projection + mask bit-pack:
//   z==0: Q (fp32 out), z==1: K (fp16 out), z==2: V (fp16 hi/lo out),
//   z==3: mask bit-pack (overlaps its DRAM stream with the compute CTAs)
__global__ __launch_bounds__(256, 2)
void gemm_qkv_kernel(const float* __restrict__ q, const float* __restrict__ k,
                     const float* __restrict__ v, const float* __restrict__ Wq,
                     const float* __restrict__ Wk, const float* __restrict__ Wv,
                     float* __restrict__ Qo, __half* __restrict__ Kh,
                     __half* __restrict__ Vh, __half* __restrict__ Vl,
                     const int* __restrict__ mask, uint32_t* __restrict__ mp)
{
    const int z = blockIdx.z;
    if (z == 3) {
        const int lane = threadIdx.x & 31;
        const int cta  = blockIdx.y * gridDim.x + blockIdx.x;     // 0..255
        const int wgid = (cta * (int)blockDim.x + (int)threadIdx.x) >> 5;
        const int nw   = (256 * 256) >> 5;                        // 2048 warps
        for (int w = wgid; w < MP_WORDS; w += nw) {
            int vv = mask[(size_t)w * 32 + lane];
            uint32_t bits = __ballot_sync(0xffffffffu, vv != 0);
            if (lane == 0) mp[w] = bits;
        }
        return;
    }
    const int bm = blockIdx.y * 64, bn = blockIdx.x * 128;
    if (z == 0)      gemm_body<0>(q, Wq, Qo, nullptr, nullptr, bm, bn);
    else if (z == 1) gemm_body<1>(k, Wk, nullptr, Kh, nullptr, bm, bn);
    else             gemm_body<2>(v, Wv, nullptr, Vh, Vl, bm, bn);
}

__global__ __launch_bounds__(256, 2)
void gemm_mma_kernel(const float* __restrict__ A, const float* __restrict__ B,
                     float* __restrict__ C)
{
    gemm_body<0>(A, B, C, nullptr, nullptr, blockIdx.y * 64, blockIdx.x * 128);
}

// ===========================================================================
// Tensor-core flash attention v8: K/V arrive PRE-CONVERTED fp16 from the
// projection epilogues -> staging is raw uint4 copies (no cvt, half traffic).
//  - S = QK^T: Q fp16 2-split (regs), K fp16 single plane.
//  - PV: P single fp16 (direct from S accums), V fp16 hi/lo planes.
// ===========================================================================
#define KROWB  144
#define PLANE  (64 * KROWB)          // 9216
#define KBUFB  PLANE                 // K: hi only
#define VBUFB  (2 * PLANE)           // V: hi+lo
#define OFF_V  (2 * KBUFB)           // 18432
#define ATTN_SMEM (2 * KBUFB + 2 * VBUFB)   // 55296

__global__ __launch_bounds__(256, 2)
void attn_mma_kernel(const float* __restrict__ Q, const __half* __restrict__ Kh,
                     const __half* __restrict__ Vh, const __half* __restrict__ Vl,
                     const uint32_t* __restrict__ Mp, float* __restrict__ O)
{
    extern __shared__ char smem[];
    const uint32_t sbase = smem_u32(smem);

    const int tid  = threadIdx.x;
    const int lane = tid & 31;
    const int wid  = tid >> 5;
    const int g    = lane >> 2;
    const int t4   = lane & 3;
    const int h    = blockIdx.y;
    const int qb   = blockIdx.x;
    const int hb   = h * HD;
    const int row0 = qb * 128 + wid * 16;

    // ---- Q fragments: fp16 hi/lo, resident in regs ----
    uint32_t qfh[4][4], qfl[4][4];
    #pragma unroll
    for (int s = 0; s < 4; ++s) {
        const float* qr0 = Q + (size_t)(row0 + g)     * EMB + hb + 16 * s + 2 * t4;
        const float* qr1 = Q + (size_t)(row0 + g + 8) * EMB + hb + 16 * s + 2 * t4;
        float x0 = qr0[0] * 0.125f, x1 = qr0[1] * 0.125f;
        float y0 = qr1[0] * 0.125f, y1 = qr1[1] * 0.125f;
        float z0 = qr0[8] * 0.125f, z1 = qr0[9] * 0.125f;
        float w0 = qr1[8] * 0.125f, w1 = qr1[9] * 0.125f;
        qfh[s][0] = cvt2h(x0, x1);
        qfl[s][0] = cvt2h(x0 - h_lowf(qfh[s][0]), x1 - h_highf(qfh[s][0]));
        qfh[s][1] = cvt2h(y0, y1);
        qfl[s][1] = cvt2h(y0 - h_lowf(qfh[s][1]), y1 - h_highf(qfh[s][1]));
        qfh[s][2] = cvt2h(z0, z1);
        qfl[s][2] = cvt2h(z0 - h_lowf(qfh[s][2]), z1 - h_highf(qfh[s][2]));
        qfh[s][3] = cvt2h(w0, w1);
        qfl[s][3] = cvt2h(w0 - h_lowf(qfh[s][3]), w1 - h_highf(qfh[s][3]));
    }

    float o[8][4];
    #pragma unroll
    for (int ni = 0; ni < 8; ++ni)
        #pragma unroll
        for (int r = 0; r < 4; ++r) o[ni][r] = 0.f;
    float m0 = -1.0e30f, m1 = -1.0e30f;
    float l0 = 0.f, l1 = 0.f;

    // staging coordinates: thread stages key row `key`, 16-dim segment qq
    const int key = tid >> 2;
    const int qq  = tid & 3;
    const __half* kb = Kh + (size_t)key * EMB + hb + qq * 16;
    const __half* vh = Vh + (size_t)key * EMB + hb + qq * 16;
    const __half* vl = Vl + (size_t)key * EMB + hb + qq * 16;

    // ldmatrix read addresses
    const int brow  = (lane & 7) + ((lane >> 4) << 3);
    const int bkoff = ((lane >> 3) & 1) * 16;
    const uint32_t kaddr0 = sbase + brow * KROWB + bkoff;
    const uint32_t vaddr0 = sbase + OFF_V + (lane & 15) * KROWB + ((lane >> 4) << 3) * 2;

    const int rbase = wid * 16 + g;
    const uint32_t* mp0 = Mp + ((size_t)h * Lq + qb * 128 + rbase) * (Lq / 32);
    const uint32_t* mp1 = mp0 + 8 * (Lq / 32);

    // raw copies: K one plane, V two planes
    #define STAGE_TILE(T, BUF) do {                                              \
        const __half* ks = kb + (size_t)(T) * 64 * EMB;                          \
        const __half* vsh = vh + (size_t)(T) * 64 * EMB;                         \
        const __half* vsl = vl + (size_t)(T) * 64 * EMB;                         \
        uint4 k0 = *(const uint4*)(ks);                                          \
        uint4 k1 = *(const uint4*)(ks + 8);                                      \
        uint4 vh0 = *(const uint4*)(vsh);                                        \
        uint4 vh1 = *(const uint4*)(vsh + 8);                                    \
        uint4 vl0 = *(const uint4*)(vsl);                                        \
        uint4 vl1 = *(const uint4*)(vsl + 8);                                    \
        char* kd = smem + (BUF) * KBUFB + key * KROWB + qq * 32;                 \
        char* vd = smem + OFF_V + (BUF) * VBUFB + key * KROWB + qq * 32;         \
        *(uint4*)(kd)              = k0;                                         \
        *(uint4*)(kd + 16)         = k1;                                         \
        *(uint4*)(vd)              = vh0;                                        \
        *(uint4*)(vd + 16)         = vh1;                                        \
        *(uint4*)(vd + PLANE)      = vl0;                                        \
        *(uint4*)(vd + PLANE + 16) = vl1;                                        \
    } while (0)

    STAGE_TILE(0, 0);
    __syncthreads();

    #pragma unroll 1
    for (int kt = 0; kt < NT; ++kt) {
        const int b = kt & 1;

        uint32_t cm0 = mp0[kt * 2],     cm1 = mp0[kt * 2 + 1];
        uint32_t cm2 = mp1[kt * 2],     cm3 = mp1[kt * 2 + 1];

        if (kt + 1 < NT) STAGE_TILE(kt + 1, b ^ 1);

        // ================= S = Q K^T (Q fp16 2-split x K fp16 single) ======
        float s[8][4];
        #pragma unroll
        for (int ni = 0; ni < 8; ++ni)
            #pragma unroll
            for (int r = 0; r < 4; ++r) s[ni][r] = 0.f;

        const uint32_t ka = kaddr0 + b * KBUFB;
        #pragma unroll
        for (int sstep = 0; sstep < 4; ++sstep) {
            #pragma unroll
            for (int p = 0; p < 4; ++p) {
                uint32_t fh[4];
                ldsm4(fh, ka + p * 16 * KROWB + sstep * 32);
                #pragma unroll
                for (int q = 0; q < 2; ++q) {
                    const int ni = 2 * p + q;
                    mma_f16(s[ni], qfh[sstep], fh[2 * q], fh[2 * q + 1]);
                    mma_f16(s[ni], qfl[sstep], fh[2 * q], fh[2 * q + 1]);
                }
            }
        }

        // ================= masked online softmax ===========================
        float tm0 = -1.0e30f, tm1 = -1.0e30f;
        #pragma unroll
        for (int ni = 0; ni < 8; ++ni) {
            uint32_t wr0 = (ni < 4) ? cm0 : cm1;
            uint32_t wr1 = (ni < 4) ? cm2 : cm3;
            int b2 = 8 * (ni & 3) + 2 * t4;
            tm0 = fmaxf(tm0, ((wr0 >> b2) & 1u)       ? -1.0e30f : s[ni][0]);
            tm0 = fmaxf(tm0, ((wr0 >> (b2 + 1)) & 1u) ? -1.0e30f : s[ni][1]);
            tm1 = fmaxf(tm1, ((wr1 >> b2) & 1u)       ? -1.0e30f : s[ni][2]);
            tm1 = fmaxf(tm1, ((wr1 >> (b2 + 1)) & 1u) ? -1.0e30f : s[ni][3]);
        }
        tm0 = fmaxf(tm0, __shfl_xor_sync(0xffffffffu, tm0, 1));
        tm0 = fmaxf(tm0, __shfl_xor_sync(0xffffffffu, tm0, 2));
        tm1 = fmaxf(tm1, __shfl_xor_sync(0xffffffffu, tm1, 1));
        tm1 = fmaxf(tm1, __shfl_xor_sync(0xffffffffu, tm1, 2));

        float mn0 = fmaxf(m0, tm0), mn1 = fmaxf(m1, tm1);
        float c0 = __expf(m0 - mn0), c1 = __expf(m1 - mn1);
        m0 = mn0; m1 = mn1;

        float rs0 = 0.f, rs1 = 0.f;
        #pragma unroll
        for (int ni = 0; ni < 8; ++ni) {
            uint32_t wr0 = (ni < 4) ? cm0 : cm1;
            uint32_t wr1 = (ni < 4) ? cm2 : cm3;
            int b2 = 8 * (ni & 3) + 2 * t4;
            float p0 = ((wr0 >> b2) & 1u)       ? 0.f : __expf(s[ni][0] - mn0);
            float p1 = ((wr0 >> (b2 + 1)) & 1u) ? 0.f : __expf(s[ni][1] - mn0);
            float p2 = ((wr1 >> b2) & 1u)       ? 0.f : __expf(s[ni][2] - mn1);
            float p3 = ((wr1 >> (b2 + 1)) & 1u) ? 0.f : __expf(s[ni][3] - mn1);
            s[ni][0] = p0; s[ni][1] = p1; s[ni][2] = p2; s[ni][3] = p3;
            rs0 += p0 + p1; rs1 += p2 + p3;
        }
        rs0 += __shfl_xor_sync(0xffffffffu, rs0, 1);
        rs0 += __shfl_xor_sync(0xffffffffu, rs0, 2);
        rs1 += __shfl_xor_sync(0xffffffffu, rs1, 1);
        rs1 += __shfl_xor_sync(0xffffffffu, rs1, 2);
        l0 = l0 * c0 + rs0;
        l1 = l1 * c1 + rs1;

        #pragma unroll
        for (int ni = 0; ni < 8; ++ni) {
            o[ni][0] *= c0; o[ni][1] *= c0;
            o[ni][2] *= c1; o[ni][3] *= c1;
        }

        // ================= O += P V (P single fp16, V fp16 2-split) ========
        {
            const uint32_t va = vaddr0 + b * VBUFB;
            #pragma unroll
            for (int st = 0; st < 4; ++st) {
                uint32_t ah[4];
                ah[0] = cvt2h(s[2 * st][0],     s[2 * st][1]);
                ah[1] = cvt2h(s[2 * st][2],     s[2 * st][3]);
                ah[2] = cvt2h(s[2 * st + 1][0], s[2 * st + 1][1]);
                ah[3] = cvt2h(s[2 * st + 1][2], s[2 * st + 1][3]);
                #pragma unroll
                for (int np = 0; np < 4; ++np) {
                    uint32_t bh[4], bl[4];
                    ldsm4t(bh, va + st * (16 * KROWB) + np * 32);
                    ldsm4t(bl, va + st * (16 * KROWB) + np * 32 + PLANE);
                    mma_f16(o[2 * np],     ah, bh[0], bh[1]);
                    mma_f16(o[2 * np],     ah, bl[0], bl[1]);
                    mma_f16(o[2 * np + 1], ah, bh[2], bh[3]);
                    mma_f16(o[2 * np + 1], ah, bl[2], bl[3]);
                }
            }
        }

        __syncthreads();
    }

    // ================= epilogue =================
    float inv0 = (l0 > 0.f) ? (1.f / l0) : 0.f;
    float inv1 = (l1 > 0.f) ? (1.f / l1) : 0.f;
    #pragma unroll
    for (int ni = 0; ni < 8; ++ni) {
        int col = hb + 8 * ni + 2 * t4;
        *(float2*)(O + (size_t)(row0 + g)     * EMB + col) =
            make_float2(o[ni][0] * inv0, o[ni][1] * inv0);
        *(float2*)(O + (size_t)(row0 + g + 8) * EMB + col) =
            make_float2(o[ni][2] * inv1, o[ni][3] * inv1);
    }
}

// ---------------------------------------------------------------------------
extern "C" void kernel_launch(void* const* d_in, const int* in_sizes, int n_in,
                              void* d_out, int out_size)
{
    const float* q    = (const float*)d_in[0];
    const float* k    = (const float*)d_in[1];
    const float* v    = (const float*)d_in[2];
    const int*   mask = (const int*)d_in[3];
    const float* Wq   = (const float*)d_in[4];
    const float* Wk   = (const float*)d_in[5];
    const float* Wv   = (const float*)d_in[6];
    const float* Wo   = (const float*)d_in[7];
    float*       out  = (float*)d_out;

    float *gQ, *gA;
    __half *gKh, *gVh, *gVl;
    uint32_t* gMp;
    cudaGetSymbolAddress((void**)&gQ,  g_Q);
    cudaGetSymbolAddress((void**)&gKh, g_Kh);
    cudaGetSymbolAddress((void**)&gVh, g_Vh);
    cudaGetSymbolAddress((void**)&gVl, g_Vl);
    cudaGetSymbolAddress((void**)&gA,  g_A);
    cudaGetSymbolAddress((void**)&gMp, g_Mp);

    cudaFuncSetAttribute(attn_mma_kernel,
                         cudaFuncAttributeMaxDynamicSharedMemorySize, ATTN_SMEM);

    dim3 qkvgrid(EMB / 128, Lq / 64, 4);   // (8, 32, 4): 3 gemms + maskpack
    gemm_qkv_kernel<<<qkvgrid, 256>>>(q, k, v, Wq, Wk, Wv,
                                      gQ, gKh, gVh, gVl, mask, gMp);

    dim3 agrid(Lq / 128, NHEAD);           // (16, 16)
    attn_mma_kernel<<<agrid, 256, ATTN_SMEM>>>(gQ, gKh, gVh, gVl, gMp, gA);

    dim3 ggrid(EMB / 128, Lq / 64);        // (8, 32)
    gemm_mma_kernel<<<ggrid, 256>>>(gA, Wo, out);
}

// round 15
// speedup vs baseline: 1.3472x; 1.3472x over previous
#include <cuda_runtime.h>
#include <cuda_bf16.h>
#include <cuda_fp16.h>
#include <stdint.h>

#define Lq     2048
#define EMB    1024
#define NHEAD  16
#define HD     64
#define NT     (Lq / 64)                       // key tiles
#define MP_WORDS (NHEAD * Lq * (Lq / 32))      // packed mask words

// Scratch (allocation-free rule: device globals)
__device__ float    g_Q[Lq * EMB];
__device__ __half   g_Kh[Lq * EMB];            // K projection, fp16
__device__ __half   g_Vh[Lq * EMB];            // V projection, fp16 hi
__device__ __half   g_Vl[Lq * EMB];            // V projection, fp16 lo
__device__ float    g_A[Lq * EMB];
__device__ uint32_t g_Mp[MP_WORDS];            // bit-packed mask (8 MB)

__device__ __forceinline__ uint32_t smem_u32(const void* p) {
    uint32_t a;
    asm("{ .reg .u64 t; cvta.to.shared.u64 t, %1; cvt.u32.u64 %0, t; }" : "=r"(a) : "l"(p));
    return a;
}
__device__ __forceinline__ uint32_t cvt2bf(float x0, float x1) {
    uint32_t r;
    asm("cvt.rn.bf16x2.f32 %0, %1, %2;" : "=r"(r) : "f"(x1), "f"(x0));
    return r;
}
__device__ __forceinline__ float bf_lowf(uint32_t h)  { return __uint_as_float(h << 16); }
__device__ __forceinline__ float bf_highf(uint32_t h) { return __uint_as_float(h & 0xffff0000u); }

__device__ __forceinline__ uint32_t cvt2h(float x0, float x1) {
    __half2 h = __floats2half2_rn(x0, x1);
    return *reinterpret_cast<uint32_t*>(&h);
}
__device__ __forceinline__ float h_lowf(uint32_t h) {
    __half2 hh = *reinterpret_cast<__half2*>(&h);
    return __low2float(hh);
}
__device__ __forceinline__ float h_highf(uint32_t h) {
    __half2 hh = *reinterpret_cast<__half2*>(&h);
    return __high2float(hh);
}

// m16n8k16 bf16 HMMA (GEMM path)
__device__ __forceinline__ void mma_bf16(float d[4], const uint32_t a[4],
                                         const uint32_t b0, const uint32_t b1) {
    asm volatile(
        "mma.sync.aligned.m16n8k16.row.col.f32.bf16.bf16.f32 "
        "{%0,%1,%2,%3}, {%4,%5,%6,%7}, {%8,%9}, {%0,%1,%2,%3};\n"
        : "+f"(d[0]), "+f"(d[1]), "+f"(d[2]), "+f"(d[3])
        : "r"(a[0]), "r"(a[1]), "r"(a[2]), "r"(a[3]), "r"(b0), "r"(b1));
}
// m16n8k16 fp16 HMMA (attention path)
__device__ __forceinline__ void mma_f16(float d[4], const uint32_t a[4],
                                        const uint32_t b0, const uint32_t b1) {
    asm volatile(
        "mma.sync.aligned.m16n8k16.row.col.f32.f16.f16.f32 "
        "{%0,%1,%2,%3}, {%4,%5,%6,%7}, {%8,%9}, {%0,%1,%2,%3};\n"
        : "+f"(d[0]), "+f"(d[1]), "+f"(d[2]), "+f"(d[3])
        : "r"(a[0]), "r"(a[1]), "r"(a[2]), "r"(a[3]), "r"(b0), "r"(b1));
}

__device__ __forceinline__ void ldsm4(uint32_t r[4], uint32_t addr) {
    asm volatile("ldmatrix.sync.aligned.m8n8.x4.shared.b16 {%0,%1,%2,%3}, [%4];"
                 : "=r"(r[0]), "=r"(r[1]), "=r"(r[2]), "=r"(r[3]) : "r"(addr));
}
__device__ __forceinline__ void ldsm4t(uint32_t r[4], uint32_t addr) {
    asm volatile("ldmatrix.sync.aligned.m8n8.x4.trans.shared.b16 {%0,%1,%2,%3}, [%4];"
                 : "=r"(r[0]), "=r"(r[1]), "=r"(r[2]), "=r"(r[3]) : "r"(addr));
}

// ===========================================================================
// Mask bit-pack: int32[H*L*L] -> u32 bits (ballot). Standalone, 16K warps to
// saturate DRAM (fusing it into the GEMM grid cut MLP 8x and cost 400us).
// ===========================================================================
__global__ __launch_bounds__(256)
void maskpack_kernel(const int* __restrict__ mask, uint32_t* __restrict__ mp)
{
    const int lane = threadIdx.x & 31;
    const int wgid = (blockIdx.x * blockDim.x + threadIdx.x) >> 5;
    const int nw   = (gridDim.x * blockDim.x) >> 5;
    for (int w = wgid; w < MP_WORDS; w += nw) {
        int v = mask[(size_t)w * 32 + lane];
        uint32_t bits = __ballot_sync(0xffffffffu, v != 0);
        if (lane == 0) mp[w] = bits;
    }
}

// ===========================================================================
// bf16 3xsplit NT GEMM body (validated R9-R13). BK=32.
// CTA tile 64x128, 8 warps (2m x 4n), warp 32x32.
// MODE 0: fp32 C.  MODE 1: fp16 C (Ch).  MODE 2: fp16 hi/lo C (Ch, Cl).
// ===========================================================================
template<int MODE>
__device__ __forceinline__ void gemm_body(const float* __restrict__ A,
                                          const float* __restrict__ B,
                                          float* __restrict__ C,
                                          __half* __restrict__ Ch,
                                          __half* __restrict__ Cl,
                                          int bm, int bn)
{
    __shared__ uint32_t Ah[64][20],  Al[64][20];    // 64 rows x 80B
    __shared__ uint32_t Bh[128][20], Bl[128][20];   // 128 rows x 80B

    const int tid  = threadIdx.x;
    const int lane = tid & 31;
    const int wid  = tid >> 5;
    const int g    = lane >> 2;
    const int t4   = lane & 3;
    const int wm   = (wid & 1) * 32;
    const int wn   = (wid >> 1) * 32;

    const int ar = tid >> 2, aw = tid & 3;
    const int br = tid >> 1, bw = tid & 1;
    const float* ap = A + (size_t)(bm + ar) * EMB + aw * 4;
    const float* bp = B + (size_t)(bn + br) * EMB + bw * 16;

    const uint32_t sAh = smem_u32(Ah), sAl = smem_u32(Al);
    const uint32_t sBh = smem_u32(Bh), sBl = smem_u32(Bl);
    const int arow = lane & 15, akoff = (lane >> 4) * 16;
    const int brow = (lane & 7) + ((lane >> 4) << 3);
    const int bkoff = ((lane >> 3) & 1) * 16;
    uint32_t aAh[2], aAl[2], aBh[2], aBl[2];
    #pragma unroll
    for (int mi = 0; mi < 2; ++mi) {
        aAh[mi] = sAh + (wm + 16 * mi + arow) * 80 + akoff;
        aAl[mi] = sAl + (wm + 16 * mi + arow) * 80 + akoff;
    }
    #pragma unroll
    for (int p = 0; p < 2; ++p) {
        aBh[p] = sBh + (wn + 16 * p + brow) * 80 + bkoff;
        aBl[p] = sBl + (wn + 16 * p + brow) * 80 + bkoff;
    }

    float d[2][4][4];
    #pragma unroll
    for (int i = 0; i < 2; ++i)
        #pragma unroll
        for (int j = 0; j < 4; ++j)
            #pragma unroll
            for (int r = 0; r < 4; ++r) d[i][j][r] = 0.f;

    float4 pa0 = *(const float4*)(ap);
    float4 pa1 = *(const float4*)(ap + 16);
    float4 pb0 = *(const float4*)(bp);
    float4 pb1 = *(const float4*)(bp + 4);
    float4 pb2 = *(const float4*)(bp + 8);
    float4 pb3 = *(const float4*)(bp + 12);

    #pragma unroll 1
    for (int c = 0; c < EMB / 32; ++c) {
        __syncthreads();
        {
            uint32_t h0 = cvt2bf(pa0.x, pa0.y), h1 = cvt2bf(pa0.z, pa0.w);
            uint32_t l0 = cvt2bf(pa0.x - bf_lowf(h0), pa0.y - bf_highf(h0));
            uint32_t l1 = cvt2bf(pa0.z - bf_lowf(h1), pa0.w - bf_highf(h1));
            *(uint2*)&Ah[ar][aw * 2] = make_uint2(h0, h1);
            *(uint2*)&Al[ar][aw * 2] = make_uint2(l0, l1);
            h0 = cvt2bf(pa1.x, pa1.y); h1 = cvt2bf(pa1.z, pa1.w);
            l0 = cvt2bf(pa1.x - bf_lowf(h0), pa1.y - bf_highf(h0));
            l1 = cvt2bf(pa1.z - bf_lowf(h1), pa1.w - bf_highf(h1));
            *(uint2*)&Ah[ar][aw * 2 + 8] = make_uint2(h0, h1);
            *(uint2*)&Al[ar][aw * 2 + 8] = make_uint2(l0, l1);

            uint32_t bh0 = cvt2bf(pb0.x, pb0.y), bh1 = cvt2bf(pb0.z, pb0.w);
            uint32_t bh2 = cvt2bf(pb1.x, pb1.y), bh3 = cvt2bf(pb1.z, pb1.w);
            uint32_t bh4 = cvt2bf(pb2.x, pb2.y), bh5 = cvt2bf(pb2.z, pb2.w);
            uint32_t bh6 = cvt2bf(pb3.x, pb3.y), bh7 = cvt2bf(pb3.z, pb3.w);
            uint32_t bl0 = cvt2bf(pb0.x - bf_lowf(bh0), pb0.y - bf_highf(bh0));
            uint32_t bl1 = cvt2bf(pb0.z - bf_lowf(bh1), pb0.w - bf_highf(bh1));
            uint32_t bl2 = cvt2bf(pb1.x - bf_lowf(bh2), pb1.y - bf_highf(bh2));
            uint32_t bl3 = cvt2bf(pb1.z - bf_lowf(bh3), pb1.w - bf_highf(bh3));
            uint32_t bl4 = cvt2bf(pb2.x - bf_lowf(bh4), pb2.y - bf_highf(bh4));
            uint32_t bl5 = cvt2bf(pb2.z - bf_lowf(bh5), pb2.w - bf_highf(bh5));
            uint32_t bl6 = cvt2bf(pb3.x - bf_lowf(bh6), pb3.y - bf_highf(bh6));
            uint32_t bl7 = cvt2bf(pb3.z - bf_lowf(bh7), pb3.w - bf_highf(bh7));
            *(uint4*)&Bh[br][bw * 8]     = make_uint4(bh0, bh1, bh2, bh3);
            *(uint4*)&Bh[br][bw * 8 + 4] = make_uint4(bh4, bh5, bh6, bh7);
            *(uint4*)&Bl[br][bw * 8]     = make_uint4(bl0, bl1, bl2, bl3);
            *(uint4*)&Bl[br][bw * 8 + 4] = make_uint4(bl4, bl5, bl6, bl7);
        }
        if (c + 1 < EMB / 32) {
            pa0 = *(const float4*)(ap + (c + 1) * 32);
            pa1 = *(const float4*)(ap + (c + 1) * 32 + 16);
            pb0 = *(const float4*)(bp + (c + 1) * 32);
            pb1 = *(const float4*)(bp + (c + 1) * 32 + 4);
            pb2 = *(const float4*)(bp + (c + 1) * 32 + 8);
            pb3 = *(const float4*)(bp + (c + 1) * 32 + 12);
        }
        __syncthreads();

        #pragma unroll
        for (int kk = 0; kk < 2; ++kk) {
            uint32_t fah[2][4], fal[2][4], fbh[2][4], fbl[2][4];
            #pragma unroll
            for (int mi = 0; mi < 2; ++mi) {
                ldsm4(fah[mi], aAh[mi] + kk * 32);
                ldsm4(fal[mi], aAl[mi] + kk * 32);
            }
            #pragma unroll
            for (int p = 0; p < 2; ++p) {
                ldsm4(fbh[p], aBh[p] + kk * 32);
                ldsm4(fbl[p], aBl[p] + kk * 32);
            }
            #pragma unroll
            for (int mi = 0; mi < 2; ++mi) {
                #pragma unroll
                for (int ni = 0; ni < 4; ++ni) {
                    const int p = ni >> 1, q = (ni & 1) * 2;
                    uint32_t b0h = fbh[p][q], b1h = fbh[p][q + 1];
                    uint32_t b0l = fbl[p][q], b1l = fbl[p][q + 1];
                    mma_bf16(d[mi][ni], fah[mi], b0h, b1h);
                    mma_bf16(d[mi][ni], fah[mi], b0l, b1l);
                    mma_bf16(d[mi][ni], fal[mi], b0h, b1h);
                }
            }
        }
    }

    #pragma unroll
    for (int mi = 0; mi < 2; ++mi) {
        int m = bm + wm + mi * 16 + g;
        #pragma unroll
        for (int ni = 0; ni < 4; ++ni) {
            int n = bn + wn + ni * 8 + 2 * t4;
            if (MODE == 0) {
                *(float2*)(C + (size_t)m * EMB + n) =
                    make_float2(d[mi][ni][0], d[mi][ni][1]);
                *(float2*)(C + (size_t)(m + 8) * EMB + n) =
                    make_float2(d[mi][ni][2], d[mi][ni][3]);
            } else if (MODE == 1) {
                *(uint32_t*)(Ch + (size_t)m * EMB + n) =
                    cvt2h(d[mi][ni][0], d[mi][ni][1]);
                *(uint32_t*)(Ch + (size_t)(m + 8) * EMB + n) =
                    cvt2h(d[mi][ni][2], d[mi][ni][3]);
            } else {
                uint32_t vh0 = cvt2h(d[mi][ni][0], d[mi][ni][1]);
                uint32_t vl0 = cvt2h(d[mi][ni][0] - h_lowf(vh0),
                                     d[mi][ni][1] - h_highf(vh0));
                uint32_t vh1 = cvt2h(d[mi][ni][2], d[mi][ni][3]);
                uint32_t vl1 = cvt2h(d[mi][ni][2] - h_lowf(vh1),
                                     d[mi][ni][3] - h_highf(vh1));
                *(uint32_t*)(Ch + (size_t)m * EMB + n)       = vh0;
                *(uint32_t*)(Cl + (size_t)m * EMB + n)       = vl0;
                *(uint32_t*)(Ch + (size_t)(m + 8) * EMB + n) = vh1;
                *(uint32_t*)(Cl + (size_t)(m + 8) * EMB + n) = vl1;
            }
        }
    }
}

// fused QKV projection: z==0 Q (fp32), z==1 K (fp16), z==2 V (fp16 hi/lo)
__global__ __launch_bounds__(256, 2)
void gemm_qkv_kernel(const float* __restrict__ q, const float* __restrict__ k,
                     const float* __restrict__ v, const float* __restrict__ Wq,
                     const float* __restrict__ Wk, const float* __restrict__ Wv,
                     float* __restrict__ Qo, __half* __restrict__ Kh,
                     __half* __restrict__ Vh, __half* __restrict__ Vl)
{
    const int z = blockIdx.z;
    const int bm = blockIdx.y * 64, bn = blockIdx.x * 128;
    if (z == 0)      gemm_body<0>(q, Wq, Qo, nullptr, nullptr, bm, bn);
    else if (z == 1) gemm_body<1>(k, Wk, nullptr, Kh, nullptr, bm, bn);
    else             gemm_body<2>(v, Wv, nullptr, Vh, Vl, bm, bn);
}

__global__ __launch_bounds__(256, 2)
void gemm_mma_kernel(const float* __restrict__ A, const float* __restrict__ B,
                     float* __restrict__ C)
{
    gemm_body<0>(A, B, C, nullptr, nullptr, blockIdx.y * 64, blockIdx.x * 128);
}

// ===========================================================================
// Tensor-core flash attention v8: K/V arrive PRE-CONVERTED fp16 from the
// projection epilogues -> staging is raw uint4 copies (no cvt, half traffic).
//  - S = QK^T: Q fp16 2-split (regs), K fp16 single plane.
//  - PV: P single fp16 (direct from S accums), V fp16 hi/lo planes.
// ===========================================================================
#define KROWB  144
#define PLANE  (64 * KROWB)          // 9216
#define KBUFB  PLANE                 // K: hi only
#define VBUFB  (2 * PLANE)           // V: hi+lo
#define OFF_V  (2 * KBUFB)           // 18432
#define ATTN_SMEM (2 * KBUFB + 2 * VBUFB)   // 55296

__global__ __launch_bounds__(256, 2)
void attn_mma_kernel(const float* __restrict__ Q, const __half* __restrict__ Kh,
                     const __half* __restrict__ Vh, const __half* __restrict__ Vl,
                     const uint32_t* __restrict__ Mp, float* __restrict__ O)
{
    extern __shared__ char smem[];
    const uint32_t sbase = smem_u32(smem);

    const int tid  = threadIdx.x;
    const int lane = tid & 31;
    const int wid  = tid >> 5;
    const int g    = lane >> 2;
    const int t4   = lane & 3;
    const int h    = blockIdx.y;
    const int qb   = blockIdx.x;
    const int hb   = h * HD;
    const int row0 = qb * 128 + wid * 16;

    // ---- Q fragments: fp16 hi/lo, resident in regs ----
    uint32_t qfh[4][4], qfl[4][4];
    #pragma unroll
    for (int s = 0; s < 4; ++s) {
        const float* qr0 = Q + (size_t)(row0 + g)     * EMB + hb + 16 * s + 2 * t4;
        const float* qr1 = Q + (size_t)(row0 + g + 8) * EMB + hb + 16 * s + 2 * t4;
        float x0 = qr0[0] * 0.125f, x1 = qr0[1] * 0.125f;
        float y0 = qr1[0] * 0.125f, y1 = qr1[1] * 0.125f;
        float z0 = qr0[8] * 0.125f, z1 = qr0[9] * 0.125f;
        float w0 = qr1[8] * 0.125f, w1 = qr1[9] * 0.125f;
        qfh[s][0] = cvt2h(x0, x1);
        qfl[s][0] = cvt2h(x0 - h_lowf(qfh[s][0]), x1 - h_highf(qfh[s][0]));
        qfh[s][1] = cvt2h(y0, y1);
        qfl[s][1] = cvt2h(y0 - h_lowf(qfh[s][1]), y1 - h_highf(qfh[s][1]));
        qfh[s][2] = cvt2h(z0, z1);
        qfl[s][2] = cvt2h(z0 - h_lowf(qfh[s][2]), z1 - h_highf(qfh[s][2]));
        qfh[s][3] = cvt2h(w0, w1);
        qfl[s][3] = cvt2h(w0 - h_lowf(qfh[s][3]), w1 - h_highf(qfh[s][3]));
    }

    float o[8][4];
    #pragma unroll
    for (int ni = 0; ni < 8; ++ni)
        #pragma unroll
        for (int r = 0; r < 4; ++r) o[ni][r] = 0.f;
    float m0 = -1.0e30f, m1 = -1.0e30f;
    float l0 = 0.f, l1 = 0.f;

    // staging coordinates: thread stages key row `key`, 16-dim segment qq
    const int key = tid >> 2;
    const int qq  = tid & 3;
    const __half* kb = Kh + (size_t)key * EMB + hb + qq * 16;
    const __half* vh = Vh + (size_t)key * EMB + hb + qq * 16;
    const __half* vl = Vl + (size_t)key * EMB + hb + qq * 16;

    // ldmatrix read addresses
    const int brow  = (lane & 7) + ((lane >> 4) << 3);
    const int bkoff = ((lane >> 3) & 1) * 16;
    const uint32_t kaddr0 = sbase + brow * KROWB + bkoff;
    const uint32_t vaddr0 = sbase + OFF_V + (lane & 15) * KROWB + ((lane >> 4) << 3) * 2;

    const int rbase = wid * 16 + g;
    const uint32_t* mp0 = Mp + ((size_t)h * Lq + qb * 128 + rbase) * (Lq / 32);
    const uint32_t* mp1 = mp0 + 8 * (Lq / 32);

    // raw copies: K one plane, V two planes
    #define STAGE_TILE(T, BUF) do {                                              \
        const __half* ks = kb + (size_t)(T) * 64 * EMB;                          \
        const __half* vsh = vh + (size_t)(T) * 64 * EMB;                         \
        const __half* vsl = vl + (size_t)(T) * 64 * EMB;                         \
        uint4 k0 = *(const uint4*)(ks);                                          \
        uint4 k1 = *(const uint4*)(ks + 8);                                      \
        uint4 vh0 = *(const uint4*)(vsh);                                        \
        uint4 vh1 = *(const uint4*)(vsh + 8);                                    \
        uint4 vl0 = *(const uint4*)(vsl);                                        \
        uint4 vl1 = *(const uint4*)(vsl + 8);                                    \
        char* kd = smem + (BUF) * KBUFB + key * KROWB + qq * 32;                 \
        char* vd = smem + OFF_V + (BUF) * VBUFB + key * KROWB + qq * 32;         \
        *(uint4*)(kd)              = k0;                                         \
        *(uint4*)(kd + 16)         = k1;                                         \
        *(uint4*)(vd)              = vh0;                                        \
        *(uint4*)(vd + 16)         = vh1;                                        \
        *(uint4*)(vd + PLANE)      = vl0;                                        \
        *(uint4*)(vd + PLANE + 16) = vl1;                                        \
    } while (0)

    STAGE_TILE(0, 0);
    __syncthreads();

    #pragma unroll 1
    for (int kt = 0; kt < NT; ++kt) {
        const int b = kt & 1;

        uint32_t cm0 = mp0[kt * 2],     cm1 = mp0[kt * 2 + 1];
        uint32_t cm2 = mp1[kt * 2],     cm3 = mp1[kt * 2 + 1];

        if (kt + 1 < NT) STAGE_TILE(kt + 1, b ^ 1);

        // ================= S = Q K^T (Q fp16 2-split x K fp16 single) ======
        float s[8][4];
        #pragma unroll
        for (int ni = 0; ni < 8; ++ni)
            #pragma unroll
            for (int r = 0; r < 4; ++r) s[ni][r] = 0.f;

        const uint32_t ka = kaddr0 + b * KBUFB;
        #pragma unroll
        for (int sstep = 0; sstep < 4; ++sstep) {
            #pragma unroll
            for (int p = 0; p < 4; ++p) {
                uint32_t fh[4];
                ldsm4(fh, ka + p * 16 * KROWB + sstep * 32);
                #pragma unroll
                for (int q = 0; q < 2; ++q) {
                    const int ni = 2 * p + q;
                    mma_f16(s[ni], qfh[sstep], fh[2 * q], fh[2 * q + 1]);
                    mma_f16(s[ni], qfl[sstep], fh[2 * q], fh[2 * q + 1]);
                }
            }
        }

        // ================= masked online softmax ===========================
        float tm0 = -1.0e30f, tm1 = -1.0e30f;
        #pragma unroll
        for (int ni = 0; ni < 8; ++ni) {
            uint32_t wr0 = (ni < 4) ? cm0 : cm1;
            uint32_t wr1 = (ni < 4) ? cm2 : cm3;
            int b2 = 8 * (ni & 3) + 2 * t4;
            tm0 = fmaxf(tm0, ((wr0 >> b2) & 1u)       ? -1.0e30f : s[ni][0]);
            tm0 = fmaxf(tm0, ((wr0 >> (b2 + 1)) & 1u) ? -1.0e30f : s[ni][1]);
            tm1 = fmaxf(tm1, ((wr1 >> b2) & 1u)       ? -1.0e30f : s[ni][2]);
            tm1 = fmaxf(tm1, ((wr1 >> (b2 + 1)) & 1u) ? -1.0e30f : s[ni][3]);
        }
        tm0 = fmaxf(tm0, __shfl_xor_sync(0xffffffffu, tm0, 1));
        tm0 = fmaxf(tm0, __shfl_xor_sync(0xffffffffu, tm0, 2));
        tm1 = fmaxf(tm1, __shfl_xor_sync(0xffffffffu, tm1, 1));
        tm1 = fmaxf(tm1, __shfl_xor_sync(0xffffffffu, tm1, 2));

        float mn0 = fmaxf(m0, tm0), mn1 = fmaxf(m1, tm1);
        float c0 = __expf(m0 - mn0), c1 = __expf(m1 - mn1);
        m0 = mn0; m1 = mn1;

        float rs0 = 0.f, rs1 = 0.f;
        #pragma unroll
        for (int ni = 0; ni < 8; ++ni) {
            uint32_t wr0 = (ni < 4) ? cm0 : cm1;
            uint32_t wr1 = (ni < 4) ? cm2 : cm3;
            int b2 = 8 * (ni & 3) + 2 * t4;
            float p0 = ((wr0 >> b2) & 1u)       ? 0.f : __expf(s[ni][0] - mn0);
            float p1 = ((wr0 >> (b2 + 1)) & 1u) ? 0.f : __expf(s[ni][1] - mn0);
            float p2 = ((wr1 >> b2) & 1u)       ? 0.f : __expf(s[ni][2] - mn1);
            float p3 = ((wr1 >> (b2 + 1)) & 1u) ? 0.f : __expf(s[ni][3] - mn1);
            s[ni][0] = p0; s[ni][1] = p1; s[ni][2] = p2; s[ni][3] = p3;
            rs0 += p0 + p1; rs1 += p2 + p3;
        }
        rs0 += __shfl_xor_sync(0xffffffffu, rs0, 1);
        rs0 += __shfl_xor_sync(0xffffffffu, rs0, 2);
        rs1 += __shfl_xor_sync(0xffffffffu, rs1, 1);
        rs1 += __shfl_xor_sync(0xffffffffu, rs1, 2);
        l0 = l0 * c0 + rs0;
        l1 = l1 * c1 + rs1;

        #pragma unroll
        for (int ni = 0; ni < 8; ++ni) {
            o[ni][0] *= c0; o[ni][1] *= c0;
            o[ni][2] *= c1; o[ni][3] *= c1;
        }

        // ================= O += P V (P single fp16, V fp16 2-split) ========
        {
            const uint32_t va = vaddr0 + b * VBUFB;
            #pragma unroll
            for (int st = 0; st < 4; ++st) {
                uint32_t ah[4];
                ah[0] = cvt2h(s[2 * st][0],     s[2 * st][1]);
                ah[1] = cvt2h(s[2 * st][2],     s[2 * st][3]);
                ah[2] = cvt2h(s[2 * st + 1][0], s[2 * st + 1][1]);
                ah[3] = cvt2h(s[2 * st + 1][2], s[2 * st + 1][3]);
                #pragma unroll
                for (int np = 0; np < 4; ++np) {
                    uint32_t bh[4], bl[4];
                    ldsm4t(bh, va + st * (16 * KROWB) + np * 32);
                    ldsm4t(bl, va + st * (16 * KROWB) + np * 32 + PLANE);
                    mma_f16(o[2 * np],     ah, bh[0], bh[1]);
                    mma_f16(o[2 * np],     ah, bl[0], bl[1]);
                    mma_f16(o[2 * np + 1], ah, bh[2], bh[3]);
                    mma_f16(o[2 * np + 1], ah, bl[2], bl[3]);
                }
            }
        }

        __syncthreads();
    }

    // ================= epilogue =================
    float inv0 = (l0 > 0.f) ? (1.f / l0) : 0.f;
    float inv1 = (l1 > 0.f) ? (1.f / l1) : 0.f;
    #pragma unroll
    for (int ni = 0; ni < 8; ++ni) {
        int col = hb + 8 * ni + 2 * t4;
        *(float2*)(O + (size_t)(row0 + g)     * EMB + col) =
            make_float2(o[ni][0] * inv0, o[ni][1] * inv0);
        *(float2*)(O + (size_t)(row0 + g + 8) * EMB + col) =
            make_float2(o[ni][2] * inv1, o[ni][3] * inv1);
    }
}

// ---------------------------------------------------------------------------
extern "C" void kernel_launch(void* const* d_in, const int* in_sizes, int n_in,
                              void* d_out, int out_size)
{
    const float* q    = (const float*)d_in[0];
    const float* k    = (const float*)d_in[1];
    const float* v    = (const float*)d_in[2];
    const int*   mask = (const int*)d_in[3];
    const float* Wq   = (const float*)d_in[4];
    const float* Wk   = (const float*)d_in[5];
    const float* Wv   = (const float*)d_in[6];
    const float* Wo   = (const float*)d_in[7];
    float*       out  = (float*)d_out;

    float *gQ, *gA;
    __half *gKh, *gVh, *gVl;
    uint32_t* gMp;
    cudaGetSymbolAddress((void**)&gQ,  g_Q);
    cudaGetSymbolAddress((void**)&gKh, g_Kh);
    cudaGetSymbolAddress((void**)&gVh, g_Vh);
    cudaGetSymbolAddress((void**)&gVl, g_Vl);
    cudaGetSymbolAddress((void**)&gA,  g_A);
    cudaGetSymbolAddress((void**)&gMp, g_Mp);

    cudaFuncSetAttribute(attn_mma_kernel,
                         cudaFuncAttributeMaxDynamicSharedMemorySize, ATTN_SMEM);

    maskpack_kernel<<<2048, 256>>>(mask, gMp);

    dim3 qkvgrid(EMB / 128, Lq / 64, 3);   // (8, 32, 3) = 768 CTAs
    gemm_qkv_kernel<<<qkvgrid, 256>>>(q, k, v, Wq, Wk, Wv, gQ, gKh, gVh, gVl);

    dim3 agrid(Lq / 128, NHEAD);           // (16, 16)
    attn_mma_kernel<<<agrid, 256, ATTN_SMEM>>>(gQ, gKh, gVh, gVl, gMp, gA);

    dim3 ggrid(EMB / 128, Lq / 64);        // (8, 32)
    gemm_mma_kernel<<<ggrid, 256>>>(gA, Wo, out);
}

// round 16
// speedup vs baseline: 1.3617x; 1.0108x over previous
#include <cuda_runtime.h>
#include <cuda_bf16.h>
#include <cuda_fp16.h>
#include <stdint.h>

#define Lq     2048
#define EMB    1024
#define NHEAD  16
#define HD     64
#define NT     (Lq / 64)                       // key tiles
#define MP_WORDS (NHEAD * Lq * (Lq / 32))      // packed mask words

// Scratch (allocation-free rule: device globals)
__device__ float    g_Q[Lq * EMB];
__device__ __half   g_Kh[Lq * EMB];            // K projection, fp16
__device__ __half   g_Vh[Lq * EMB];            // V projection, fp16 hi
__device__ __half   g_Vl[Lq * EMB];            // V projection, fp16 lo
__device__ float    g_A[Lq * EMB];
__device__ uint32_t g_Mp[MP_WORDS];            // bit-packed mask (8 MB)

__device__ __forceinline__ uint32_t smem_u32(const void* p) {
    uint32_t a;
    asm("{ .reg .u64 t; cvta.to.shared.u64 t, %1; cvt.u32.u64 %0, t; }" : "=r"(a) : "l"(p));
    return a;
}
__device__ __forceinline__ uint32_t cvt2bf(float x0, float x1) {
    uint32_t r;
    asm("cvt.rn.bf16x2.f32 %0, %1, %2;" : "=r"(r) : "f"(x1), "f"(x0));
    return r;
}
__device__ __forceinline__ float bf_lowf(uint32_t h)  { return __uint_as_float(h << 16); }
__device__ __forceinline__ float bf_highf(uint32_t h) { return __uint_as_float(h & 0xffff0000u); }

__device__ __forceinline__ uint32_t cvt2h(float x0, float x1) {
    __half2 h = __floats2half2_rn(x0, x1);
    return *reinterpret_cast<uint32_t*>(&h);
}
__device__ __forceinline__ float h_lowf(uint32_t h) {
    __half2 hh = *reinterpret_cast<__half2*>(&h);
    return __low2float(hh);
}
__device__ __forceinline__ float h_highf(uint32_t h) {
    __half2 hh = *reinterpret_cast<__half2*>(&h);
    return __high2float(hh);
}

// m16n8k16 bf16 HMMA (GEMM path)
__device__ __forceinline__ void mma_bf16(float d[4], const uint32_t a[4],
                                         const uint32_t b0, const uint32_t b1) {
    asm volatile(
        "mma.sync.aligned.m16n8k16.row.col.f32.bf16.bf16.f32 "
        "{%0,%1,%2,%3}, {%4,%5,%6,%7}, {%8,%9}, {%0,%1,%2,%3};\n"
        : "+f"(d[0]), "+f"(d[1]), "+f"(d[2]), "+f"(d[3])
        : "r"(a[0]), "r"(a[1]), "r"(a[2]), "r"(a[3]), "r"(b0), "r"(b1));
}
// m16n8k16 fp16 HMMA (attention path)
__device__ __forceinline__ void mma_f16(float d[4], const uint32_t a[4],
                                        const uint32_t b0, const uint32_t b1) {
    asm volatile(
        "mma.sync.aligned.m16n8k16.row.col.f32.f16.f16.f32 "
        "{%0,%1,%2,%3}, {%4,%5,%6,%7}, {%8,%9}, {%0,%1,%2,%3};\n"
        : "+f"(d[0]), "+f"(d[1]), "+f"(d[2]), "+f"(d[3])
        : "r"(a[0]), "r"(a[1]), "r"(a[2]), "r"(a[3]), "r"(b0), "r"(b1));
}

__device__ __forceinline__ void ldsm4(uint32_t r[4], uint32_t addr) {
    asm volatile("ldmatrix.sync.aligned.m8n8.x4.shared.b16 {%0,%1,%2,%3}, [%4];"
                 : "=r"(r[0]), "=r"(r[1]), "=r"(r[2]), "=r"(r[3]) : "r"(addr));
}
__device__ __forceinline__ void ldsm4t(uint32_t r[4], uint32_t addr) {
    asm volatile("ldmatrix.sync.aligned.m8n8.x4.trans.shared.b16 {%0,%1,%2,%3}, [%4];"
                 : "=r"(r[0]), "=r"(r[1]), "=r"(r[2]), "=r"(r[3]) : "r"(addr));
}

// ===========================================================================
// Mask bit-pack: int32[H*L*L] -> u32 bits (ballot). Standalone, 16K warps to
// saturate DRAM (fusing into the GEMM grid cut MLP 8x and cost 400us: R14).
// ===========================================================================
__global__ __launch_bounds__(256)
void maskpack_kernel(const int* __restrict__ mask, uint32_t* __restrict__ mp)
{
    const int lane = threadIdx.x & 31;
    const int wgid = (blockIdx.x * blockDim.x + threadIdx.x) >> 5;
    const int nw   = (gridDim.x * blockDim.x) >> 5;
    for (int w = wgid; w < MP_WORDS; w += nw) {
        int v = mask[(size_t)w * 32 + lane];
        uint32_t bits = __ballot_sync(0xffffffffu, v != 0);
        if (lane == 0) mp[w] = bits;
    }
}

// ===========================================================================
// bf16 3xsplit NT GEMM body, DOUBLE-BUFFERED smem (1 sync/chunk). BK=32.
// CTA tile 64x128, 8 warps (2m x 4n), warp 32x32. Dynamic smem 2x30KB.
// MODE 0: fp32 C.  MODE 1: fp16 C (Ch).  MODE 2: fp16 hi/lo C (Ch, Cl).
// ===========================================================================
#define G_OFF_AH 0
#define G_OFF_AL 5120
#define G_OFF_BH 10240
#define G_OFF_BL 20480
#define G_BUF    30720
#define GEMM_SMEM (2 * G_BUF)    // 61440

template<int MODE>
__device__ __forceinline__ void gemm_body(const float* __restrict__ A,
                                          const float* __restrict__ B,
                                          float* __restrict__ C,
                                          __half* __restrict__ Ch,
                                          __half* __restrict__ Cl,
                                          int bm, int bn)
{
    extern __shared__ char gsm[];
    const uint32_t sb = smem_u32(gsm);

    const int tid  = threadIdx.x;
    const int lane = tid & 31;
    const int wid  = tid >> 5;
    const int g    = lane >> 2;
    const int t4   = lane & 3;
    const int wm   = (wid & 1) * 32;
    const int wn   = (wid >> 1) * 32;

    const int ar = tid >> 2, aw = tid & 3;
    const int br = tid >> 1, bw = tid & 1;
    const float* ap = A + (size_t)(bm + ar) * EMB + aw * 4;
    const float* bp = B + (size_t)(bn + br) * EMB + bw * 16;

    // ldmatrix base addresses (buffer offset added at use)
    const int arow = lane & 15, akoff = (lane >> 4) * 16;
    const int brow = (lane & 7) + ((lane >> 4) << 3);
    const int bkoff = ((lane >> 3) & 1) * 16;
    uint32_t aAh[2], aAl[2], aBh[2], aBl[2];
    #pragma unroll
    for (int mi = 0; mi < 2; ++mi) {
        aAh[mi] = sb + G_OFF_AH + (wm + 16 * mi + arow) * 80 + akoff;
        aAl[mi] = sb + G_OFF_AL + (wm + 16 * mi + arow) * 80 + akoff;
    }
    #pragma unroll
    for (int p = 0; p < 2; ++p) {
        aBh[p] = sb + G_OFF_BH + (wn + 16 * p + brow) * 80 + bkoff;
        aBl[p] = sb + G_OFF_BL + (wn + 16 * p + brow) * 80 + bkoff;
    }

    // STS byte offsets (within a buffer)
    const int sA = ar * 80 + aw * 8;        // uint2 targets (+32 for 2nd half)
    const int sB = br * 80 + bw * 32;       // uint4 targets (+16 for 2nd)

    float d[2][4][4];
    #pragma unroll
    for (int i = 0; i < 2; ++i)
        #pragma unroll
        for (int j = 0; j < 4; ++j)
            #pragma unroll
            for (int r = 0; r < 4; ++r) d[i][j][r] = 0.f;

    float4 pa0 = *(const float4*)(ap);
    float4 pa1 = *(const float4*)(ap + 16);
    float4 pb0 = *(const float4*)(bp);
    float4 pb1 = *(const float4*)(bp + 4);
    float4 pb2 = *(const float4*)(bp + 8);
    float4 pb3 = *(const float4*)(bp + 12);

    // split + store the prefetched chunk into buffer BUF
    #define GSTAGE(BUF) do {                                                     \
        char* base = gsm + (BUF) * G_BUF;                                        \
        uint32_t h0 = cvt2bf(pa0.x, pa0.y), h1 = cvt2bf(pa0.z, pa0.w);           \
        uint32_t l0 = cvt2bf(pa0.x - bf_lowf(h0), pa0.y - bf_highf(h0));         \
        uint32_t l1 = cvt2bf(pa0.z - bf_lowf(h1), pa0.w - bf_highf(h1));         \
        *(uint2*)(base + G_OFF_AH + sA) = make_uint2(h0, h1);                    \
        *(uint2*)(base + G_OFF_AL + sA) = make_uint2(l0, l1);                    \
        h0 = cvt2bf(pa1.x, pa1.y); h1 = cvt2bf(pa1.z, pa1.w);                    \
        l0 = cvt2bf(pa1.x - bf_lowf(h0), pa1.y - bf_highf(h0));                  \
        l1 = cvt2bf(pa1.z - bf_lowf(h1), pa1.w - bf_highf(h1));                  \
        *(uint2*)(base + G_OFF_AH + sA + 32) = make_uint2(h0, h1);               \
        *(uint2*)(base + G_OFF_AL + sA + 32) = make_uint2(l0, l1);               \
        uint32_t bh0 = cvt2bf(pb0.x, pb0.y), bh1 = cvt2bf(pb0.z, pb0.w);         \
        uint32_t bh2 = cvt2bf(pb1.x, pb1.y), bh3 = cvt2bf(pb1.z, pb1.w);         \
        uint32_t bh4 = cvt2bf(pb2.x, pb2.y), bh5 = cvt2bf(pb2.z, pb2.w);         \
        uint32_t bh6 = cvt2bf(pb3.x, pb3.y), bh7 = cvt2bf(pb3.z, pb3.w);         \
        uint32_t bl0 = cvt2bf(pb0.x - bf_lowf(bh0), pb0.y - bf_highf(bh0));      \
        uint32_t bl1 = cvt2bf(pb0.z - bf_lowf(bh1), pb0.w - bf_highf(bh1));      \
        uint32_t bl2 = cvt2bf(pb1.x - bf_lowf(bh2), pb1.y - bf_highf(bh2));      \
        uint32_t bl3 = cvt2bf(pb1.z - bf_lowf(bh3), pb1.w - bf_highf(bh3));      \
        uint32_t bl4 = cvt2bf(pb2.x - bf_lowf(bh4), pb2.y - bf_highf(bh4));      \
        uint32_t bl5 = cvt2bf(pb2.z - bf_lowf(bh5), pb2.w - bf_highf(bh5));      \
        uint32_t bl6 = cvt2bf(pb3.x - bf_lowf(bh6), pb3.y - bf_highf(bh6));      \
        uint32_t bl7 = cvt2bf(pb3.z - bf_lowf(bh7), pb3.w - bf_highf(bh7));      \
        *(uint4*)(base + G_OFF_BH + sB)      = make_uint4(bh0, bh1, bh2, bh3);   \
        *(uint4*)(base + G_OFF_BH + sB + 16) = make_uint4(bh4, bh5, bh6, bh7);   \
        *(uint4*)(base + G_OFF_BL + sB)      = make_uint4(bl0, bl1, bl2, bl3);   \
        *(uint4*)(base + G_OFF_BL + sB + 16) = make_uint4(bl4, bl5, bl6, bl7);   \
    } while (0)

    GSTAGE(0);
    __syncthreads();

    #pragma unroll 1
    for (int c = 0; c < EMB / 32; ++c) {
        const int b = c & 1;
        const uint32_t boff = b * G_BUF;

        // prefetch next chunk (hides under MMAs below)
        if (c + 1 < EMB / 32) {
            pa0 = *(const float4*)(ap + (c + 1) * 32);
            pa1 = *(const float4*)(ap + (c + 1) * 32 + 16);
            pb0 = *(const float4*)(bp + (c + 1) * 32);
            pb1 = *(const float4*)(bp + (c + 1) * 32 + 4);
            pb2 = *(const float4*)(bp + (c + 1) * 32 + 8);
            pb3 = *(const float4*)(bp + (c + 1) * 32 + 12);
        }

        // compute from buffer b
        #pragma unroll
        for (int kk = 0; kk < 2; ++kk) {
            uint32_t fah[2][4], fal[2][4], fbh[2][4], fbl[2][4];
            #pragma unroll
            for (int mi = 0; mi < 2; ++mi) {
                ldsm4(fah[mi], aAh[mi] + boff + kk * 32);
                ldsm4(fal[mi], aAl[mi] + boff + kk * 32);
            }
            #pragma unroll
            for (int p = 0; p < 2; ++p) {
                ldsm4(fbh[p], aBh[p] + boff + kk * 32);
                ldsm4(fbl[p], aBl[p] + boff + kk * 32);
            }
            #pragma unroll
            for (int mi = 0; mi < 2; ++mi) {
                #pragma unroll
                for (int ni = 0; ni < 4; ++ni) {
                    const int p = ni >> 1, q = (ni & 1) * 2;
                    uint32_t b0h = fbh[p][q], b1h = fbh[p][q + 1];
                    uint32_t b0l = fbl[p][q], b1l = fbl[p][q + 1];
                    mma_bf16(d[mi][ni], fah[mi], b0h, b1h);
                    mma_bf16(d[mi][ni], fah[mi], b0l, b1l);
                    mma_bf16(d[mi][ni], fal[mi], b0h, b1h);
                }
            }
        }

        // stage next chunk into the other buffer
        if (c + 1 < EMB / 32) GSTAGE(b ^ 1);
        __syncthreads();
    }

    #pragma unroll
    for (int mi = 0; mi < 2; ++mi) {
        int m = bm + wm + mi * 16 + g;
        #pragma unroll
        for (int ni = 0; ni < 4; ++ni) {
            int n = bn + wn + ni * 8 + 2 * t4;
            if (MODE == 0) {
                *(float2*)(C + (size_t)m * EMB + n) =
                    make_float2(d[mi][ni][0], d[mi][ni][1]);
                *(float2*)(C + (size_t)(m + 8) * EMB + n) =
                    make_float2(d[mi][ni][2], d[mi][ni][3]);
            } else if (MODE == 1) {
                *(uint32_t*)(Ch + (size_t)m * EMB + n) =
                    cvt2h(d[mi][ni][0], d[mi][ni][1]);
                *(uint32_t*)(Ch + (size_t)(m + 8) * EMB + n) =
                    cvt2h(d[mi][ni][2], d[mi][ni][3]);
            } else {
                uint32_t vh0 = cvt2h(d[mi][ni][0], d[mi][ni][1]);
                uint32_t vl0 = cvt2h(d[mi][ni][0] - h_lowf(vh0),
                                     d[mi][ni][1] - h_highf(vh0));
                uint32_t vh1 = cvt2h(d[mi][ni][2], d[mi][ni][3]);
                uint32_t vl1 = cvt2h(d[mi][ni][2] - h_lowf(vh1),
                                     d[mi][ni][3] - h_highf(vh1));
                *(uint32_t*)(Ch + (size_t)m * EMB + n)       = vh0;
                *(uint32_t*)(Cl + (size_t)m * EMB + n)       = vl0;
                *(uint32_t*)(Ch + (size_t)(m + 8) * EMB + n) = vh1;
                *(uint32_t*)(Cl + (size_t)(m + 8) * EMB + n) = vl1;
            }
        }
    }
    #undef GSTAGE
}

// fused QKV projection: z==0 Q (fp32), z==1 K (fp16), z==2 V (fp16 hi/lo)
__global__ __launch_bounds__(256, 2)
void gemm_qkv_kernel(const float* __restrict__ q, const float* __restrict__ k,
                     const float* __restrict__ v, const float* __restrict__ Wq,
                     const float* __restrict__ Wk, const float* __restrict__ Wv,
                     float* __restrict__ Qo, __half* __restrict__ Kh,
                     __half* __restrict__ Vh, __half* __restrict__ Vl)
{
    const int z = blockIdx.z;
    const int bm = blockIdx.y * 64, bn = blockIdx.x * 128;
    if (z == 0)      gemm_body<0>(q, Wq, Qo, nullptr, nullptr, bm, bn);
    else if (z == 1) gemm_body<1>(k, Wk, nullptr, Kh, nullptr, bm, bn);
    else             gemm_body<2>(v, Wv, nullptr, Vh, Vl, bm, bn);
}

__global__ __launch_bounds__(256, 2)
void gemm_mma_kernel(const float* __restrict__ A, const float* __restrict__ B,
                     float* __restrict__ C)
{
    gemm_body<0>(A, B, C, nullptr, nullptr, blockIdx.y * 64, blockIdx.x * 128);
}

// ===========================================================================
// Tensor-core flash attention v8 (unchanged from R15): K/V pre-converted
// fp16, raw uint4 staging, Q fp16 2-split, K single, P single, V 2-split.
// ===========================================================================
#define KROWB  144
#define PLANE  (64 * KROWB)          // 9216
#define KBUFB  PLANE                 // K: hi only
#define VBUFB  (2 * PLANE)           // V: hi+lo
#define OFF_V  (2 * KBUFB)           // 18432
#define ATTN_SMEM (2 * KBUFB + 2 * VBUFB)   // 55296

__global__ __launch_bounds__(256, 2)
void attn_mma_kernel(const float* __restrict__ Q, const __half* __restrict__ Kh,
                     const __half* __restrict__ Vh, const __half* __restrict__ Vl,
                     const uint32_t* __restrict__ Mp, float* __restrict__ O)
{
    extern __shared__ char smem[];
    const uint32_t sbase = smem_u32(smem);

    const int tid  = threadIdx.x;
    const int lane = tid & 31;
    const int wid  = tid >> 5;
    const int g    = lane >> 2;
    const int t4   = lane & 3;
    const int h    = blockIdx.y;
    const int qb   = blockIdx.x;
    const int hb   = h * HD;
    const int row0 = qb * 128 + wid * 16;

    // ---- Q fragments: fp16 hi/lo, resident in regs ----
    uint32_t qfh[4][4], qfl[4][4];
    #pragma unroll
    for (int s = 0; s < 4; ++s) {
        const float* qr0 = Q + (size_t)(row0 + g)     * EMB + hb + 16 * s + 2 * t4;
        const float* qr1 = Q + (size_t)(row0 + g + 8) * EMB + hb + 16 * s + 2 * t4;
        float x0 = qr0[0] * 0.125f, x1 = qr0[1] * 0.125f;
        float y0 = qr1[0] * 0.125f, y1 = qr1[1] * 0.125f;
        float z0 = qr0[8] * 0.125f, z1 = qr0[9] * 0.125f;
        float w0 = qr1[8] * 0.125f, w1 = qr1[9] * 0.125f;
        qfh[s][0] = cvt2h(x0, x1);
        qfl[s][0] = cvt2h(x0 - h_lowf(qfh[s][0]), x1 - h_highf(qfh[s][0]));
        qfh[s][1] = cvt2h(y0, y1);
        qfl[s][1] = cvt2h(y0 - h_lowf(qfh[s][1]), y1 - h_highf(qfh[s][1]));
        qfh[s][2] = cvt2h(z0, z1);
        qfl[s][2] = cvt2h(z0 - h_lowf(qfh[s][2]), z1 - h_highf(qfh[s][2]));
        qfh[s][3] = cvt2h(w0, w1);
        qfl[s][3] = cvt2h(w0 - h_lowf(qfh[s][3]), w1 - h_highf(qfh[s][3]));
    }

    float o[8][4];
    #pragma unroll
    for (int ni = 0; ni < 8; ++ni)
        #pragma unroll
        for (int r = 0; r < 4; ++r) o[ni][r] = 0.f;
    float m0 = -1.0e30f, m1 = -1.0e30f;
    float l0 = 0.f, l1 = 0.f;

    // staging coordinates: thread stages key row `key`, 16-dim segment qq
    const int key = tid >> 2;
    const int qq  = tid & 3;
    const __half* kb = Kh + (size_t)key * EMB + hb + qq * 16;
    const __half* vh = Vh + (size_t)key * EMB + hb + qq * 16;
    const __half* vl = Vl + (size_t)key * EMB + hb + qq * 16;

    // ldmatrix read addresses
    const int brow  = (lane & 7) + ((lane >> 4) << 3);
    const int bkoff = ((lane >> 3) & 1) * 16;
    const uint32_t kaddr0 = sbase + brow * KROWB + bkoff;
    const uint32_t vaddr0 = sbase + OFF_V + (lane & 15) * KROWB + ((lane >> 4) << 3) * 2;

    const int rbase = wid * 16 + g;
    const uint32_t* mp0 = Mp + ((size_t)h * Lq + qb * 128 + rbase) * (Lq / 32);
    const uint32_t* mp1 = mp0 + 8 * (Lq / 32);

    // raw copies: K one plane, V two planes
    #define STAGE_TILE(T, BUF) do {                                              \
        const __half* ks = kb + (size_t)(T) * 64 * EMB;                          \
        const __half* vsh = vh + (size_t)(T) * 64 * EMB;                         \
        const __half* vsl = vl + (size_t)(T) * 64 * EMB;                         \
        uint4 k0 = *(const uint4*)(ks);                                          \
        uint4 k1 = *(const uint4*)(ks + 8);                                      \
        uint4 vh0 = *(const uint4*)(vsh);                                        \
        uint4 vh1 = *(const uint4*)(vsh + 8);                                    \
        uint4 vl0 = *(const uint4*)(vsl);                                        \
        uint4 vl1 = *(const uint4*)(vsl + 8);                                    \
        char* kd = smem + (BUF) * KBUFB + key * KROWB + qq * 32;                 \
        char* vd = smem + OFF_V + (BUF) * VBUFB + key * KROWB + qq * 32;         \
        *(uint4*)(kd)              = k0;                                         \
        *(uint4*)(kd + 16)         = k1;                                         \
        *(uint4*)(vd)              = vh0;                                        \
        *(uint4*)(vd + 16)         = vh1;                                        \
        *(uint4*)(vd + PLANE)      = vl0;                                        \
        *(uint4*)(vd + PLANE + 16) = vl1;                                        \
    } while (0)

    STAGE_TILE(0, 0);
    __syncthreads();

    #pragma unroll 1
    for (int kt = 0; kt < NT; ++kt) {
        const int b = kt & 1;

        uint32_t cm0 = mp0[kt * 2],     cm1 = mp0[kt * 2 + 1];
        uint32_t cm2 = mp1[kt * 2],     cm3 = mp1[kt * 2 + 1];

        if (kt + 1 < NT) STAGE_TILE(kt + 1, b ^ 1);

        // ================= S = Q K^T (Q fp16 2-split x K fp16 single) ======
        float s[8][4];
        #pragma unroll
        for (int ni = 0; ni < 8; ++ni)
            #pragma unroll
            for (int r = 0; r < 4; ++r) s[ni][r] = 0.f;

        const uint32_t ka = kaddr0 + b * KBUFB;
        #pragma unroll
        for (int sstep = 0; sstep < 4; ++sstep) {
            #pragma unroll
            for (int p = 0; p < 4; ++p) {
                uint32_t fh[4];
                ldsm4(fh, ka + p * 16 * KROWB + sstep * 32);
                #pragma unroll
                for (int q = 0; q < 2; ++q) {
                    const int ni = 2 * p + q;
                    mma_f16(s[ni], qfh[sstep], fh[2 * q], fh[2 * q + 1]);
                    mma_f16(s[ni], qfl[sstep], fh[2 * q], fh[2 * q + 1]);
                }
            }
        }

        // ================= masked online softmax ===========================
        float tm0 = -1.0e30f, tm1 = -1.0e30f;
        #pragma unroll
        for (int ni = 0; ni < 8; ++ni) {
            uint32_t wr0 = (ni < 4) ? cm0 : cm1;
            uint32_t wr1 = (ni < 4) ? cm2 : cm3;
            int b2 = 8 * (ni & 3) + 2 * t4;
            tm0 = fmaxf(tm0, ((wr0 >> b2) & 1u)       ? -1.0e30f : s[ni][0]);
            tm0 = fmaxf(tm0, ((wr0 >> (b2 + 1)) & 1u) ? -1.0e30f : s[ni][1]);
            tm1 = fmaxf(tm1, ((wr1 >> b2) & 1u)       ? -1.0e30f : s[ni][2]);
            tm1 = fmaxf(tm1, ((wr1 >> (b2 + 1)) & 1u) ? -1.0e30f : s[ni][3]);
        }
        tm0 = fmaxf(tm0, __shfl_xor_sync(0xffffffffu, tm0, 1));
        tm0 = fmaxf(tm0, __shfl_xor_sync(0xffffffffu, tm0, 2));
        tm1 = fmaxf(tm1, __shfl_xor_sync(0xffffffffu, tm1, 1));
        tm1 = fmaxf(tm1, __shfl_xor_sync(0xffffffffu, tm1, 2));

        float mn0 = fmaxf(m0, tm0), mn1 = fmaxf(m1, tm1);
        float c0 = __expf(m0 - mn0), c1 = __expf(m1 - mn1);
        m0 = mn0; m1 = mn1;

        float rs0 = 0.f, rs1 = 0.f;
        #pragma unroll
        for (int ni = 0; ni < 8; ++ni) {
            uint32_t wr0 = (ni < 4) ? cm0 : cm1;
            uint32_t wr1 = (ni < 4) ? cm2 : cm3;
            int b2 = 8 * (ni & 3) + 2 * t4;
            float p0 = ((wr0 >> b2) & 1u)       ? 0.f : __expf(s[ni][0] - mn0);
            float p1 = ((wr0 >> (b2 + 1)) & 1u) ? 0.f : __expf(s[ni][1] - mn0);
            float p2 = ((wr1 >> b2) & 1u)       ? 0.f : __expf(s[ni][2] - mn1);
            float p3 = ((wr1 >> (b2 + 1)) & 1u) ? 0.f : __expf(s[ni][3] - mn1);
            s[ni][0] = p0; s[ni][1] = p1; s[ni][2] = p2; s[ni][3] = p3;
            rs0 += p0 + p1; rs1 += p2 + p3;
        }
        rs0 += __shfl_xor_sync(0xffffffffu, rs0, 1);
        rs0 += __shfl_xor_sync(0xffffffffu, rs0, 2);
        rs1 += __shfl_xor_sync(0xffffffffu, rs1, 1);
        rs1 += __shfl_xor_sync(0xffffffffu, rs1, 2);
        l0 = l0 * c0 + rs0;
        l1 = l1 * c1 + rs1;

        #pragma unroll
        for (int ni = 0; ni < 8; ++ni) {
            o[ni][0] *= c0; o[ni][1] *= c0;
            o[ni][2] *= c1; o[ni][3] *= c1;
        }

        // ================= O += P V (P single fp16, V fp16 2-split) ========
        {
            const uint32_t va = vaddr0 + b * VBUFB;
            #pragma unroll
            for (int st = 0; st < 4; ++st) {
                uint32_t ah[4];
                ah[0] = cvt2h(s[2 * st][0],     s[2 * st][1]);
                ah[1] = cvt2h(s[2 * st][2],     s[2 * st][3]);
                ah[2] = cvt2h(s[2 * st + 1][0], s[2 * st + 1][1]);
                ah[3] = cvt2h(s[2 * st + 1][2], s[2 * st + 1][3]);
                #pragma unroll
                for (int np = 0; np < 4; ++np) {
                    uint32_t bh[4], bl[4];
                    ldsm4t(bh, va + st * (16 * KROWB) + np * 32);
                    ldsm4t(bl, va + st * (16 * KROWB) + np * 32 + PLANE);
                    mma_f16(o[2 * np],     ah, bh[0], bh[1]);
                    mma_f16(o[2 * np],     ah, bl[0], bl[1]);
                    mma_f16(o[2 * np + 1], ah, bh[2], bh[3]);
                    mma_f16(o[2 * np + 1], ah, bl[2], bl[3]);
                }
            }
        }

        __syncthreads();
    }

    // ================= epilogue =================
    float inv0 = (l0 > 0.f) ? (1.f / l0) : 0.f;
    float inv1 = (l1 > 0.f) ? (1.f / l1) : 0.f;
    #pragma unroll
    for (int ni = 0; ni < 8; ++ni) {
        int col = hb + 8 * ni + 2 * t4;
        *(float2*)(O + (size_t)(row0 + g)     * EMB + col) =
            make_float2(o[ni][0] * inv0, o[ni][1] * inv0);
        *(float2*)(O + (size_t)(row0 + g + 8) * EMB + col) =
            make_float2(o[ni][2] * inv1, o[ni][3] * inv1);
    }
}

// ---------------------------------------------------------------------------
extern "C" void kernel_launch(void* const* d_in, const int* in_sizes, int n_in,
                              void* d_out, int out_size)
{
    const float* q    = (const float*)d_in[0];
    const float* k    = (const float*)d_in[1];
    const float* v    = (const float*)d_in[2];
    const int*   mask = (const int*)d_in[3];
    const float* Wq   = (const float*)d_in[4];
    const float* Wk   = (const float*)d_in[5];
    const float* Wv   = (const float*)d_in[6];
    const float* Wo   = (const float*)d_in[7];
    float*       out  = (float*)d_out;

    float *gQ, *gA;
    __half *gKh, *gVh, *gVl;
    uint32_t* gMp;
    cudaGetSymbolAddress((void**)&gQ,  g_Q);
    cudaGetSymbolAddress((void**)&gKh, g_Kh);
    cudaGetSymbolAddress((void**)&gVh, g_Vh);
    cudaGetSymbolAddress((void**)&gVl, g_Vl);
    cudaGetSymbolAddress((void**)&gA,  g_A);
    cudaGetSymbolAddress((void**)&gMp, g_Mp);

    cudaFuncSetAttribute(attn_mma_kernel,
                         cudaFuncAttributeMaxDynamicSharedMemorySize, ATTN_SMEM);
    cudaFuncSetAttribute(gemm_qkv_kernel,
                         cudaFuncAttributeMaxDynamicSharedMemorySize, GEMM_SMEM);
    cudaFuncSetAttribute(gemm_mma_kernel,
                         cudaFuncAttributeMaxDynamicSharedMemorySize, GEMM_SMEM);

    maskpack_kernel<<<2048, 256>>>(mask, gMp);

    dim3 qkvgrid(EMB / 128, Lq / 64, 3);   // (8, 32, 3) = 768 CTAs
    gemm_qkv_kernel<<<qkvgrid, 256, GEMM_SMEM>>>(q, k, v, Wq, Wk, Wv,
                                                 gQ, gKh, gVh, gVl);

    dim3 agrid(Lq / 128, NHEAD);           // (16, 16)
    attn_mma_kernel<<<agrid, 256, ATTN_SMEM>>>(gQ, gKh, gVh, gVl, gMp, gA);

    dim3 ggrid(EMB / 128, Lq / 64);        // (8, 32)
    gemm_mma_kernel<<<ggrid, 256, GEMM_SMEM>>>(gA, Wo, out);
}

// round 17
// speedup vs baseline: 1.4385x; 1.0564x over previous
#include <cuda_runtime.h>
#include <cuda_bf16.h>
#include <cuda_fp16.h>
#include <stdint.h>

#define Lq     2048
#define EMB    1024
#define NHEAD  16
#define HD     64
#define NT     (Lq / 64)                       // key tiles
#define MP_WORDS (NHEAD * Lq * (Lq / 32))      // packed mask words

// Scratch (allocation-free rule: device globals)
__device__ float    g_Q[Lq * EMB];
__device__ __half   g_Kh[Lq * EMB];            // K projection, fp16
__device__ __half   g_Vh[Lq * EMB];            // V projection, fp16 hi
__device__ __half   g_Vl[Lq * EMB];            // V projection, fp16 lo
__device__ float    g_A[Lq * EMB];
__device__ uint32_t g_Mp[MP_WORDS];            // bit-packed mask (8 MB)

__device__ __forceinline__ uint32_t smem_u32(const void* p) {
    uint32_t a;
    asm("{ .reg .u64 t; cvta.to.shared.u64 t, %1; cvt.u32.u64 %0, t; }" : "=r"(a) : "l"(p));
    return a;
}
__device__ __forceinline__ uint32_t cvt2bf(float x0, float x1) {
    uint32_t r;
    asm("cvt.rn.bf16x2.f32 %0, %1, %2;" : "=r"(r) : "f"(x1), "f"(x0));
    return r;
}
__device__ __forceinline__ float bf_lowf(uint32_t h)  { return __uint_as_float(h << 16); }
__device__ __forceinline__ float bf_highf(uint32_t h) { return __uint_as_float(h & 0xffff0000u); }

__device__ __forceinline__ uint32_t cvt2h(float x0, float x1) {
    __half2 h = __floats2half2_rn(x0, x1);
    return *reinterpret_cast<uint32_t*>(&h);
}
__device__ __forceinline__ float h_lowf(uint32_t h) {
    __half2 hh = *reinterpret_cast<__half2*>(&h);
    return __low2float(hh);
}
__device__ __forceinline__ float h_highf(uint32_t h) {
    __half2 hh = *reinterpret_cast<__half2*>(&h);
    return __high2float(hh);
}

// m16n8k16 bf16 HMMA (GEMM path)
__device__ __forceinline__ void mma_bf16(float d[4], const uint32_t a[4],
                                         const uint32_t b0, const uint32_t b1) {
    asm volatile(
        "mma.sync.aligned.m16n8k16.row.col.f32.bf16.bf16.f32 "
        "{%0,%1,%2,%3}, {%4,%5,%6,%7}, {%8,%9}, {%0,%1,%2,%3};\n"
        : "+f"(d[0]), "+f"(d[1]), "+f"(d[2]), "+f"(d[3])
        : "r"(a[0]), "r"(a[1]), "r"(a[2]), "r"(a[3]), "r"(b0), "r"(b1));
}
// m16n8k16 fp16 HMMA (attention path)
__device__ __forceinline__ void mma_f16(float d[4], const uint32_t a[4],
                                        const uint32_t b0, const uint32_t b1) {
    asm volatile(
        "mma.sync.aligned.m16n8k16.row.col.f32.f16.f16.f32 "
        "{%0,%1,%2,%3}, {%4,%5,%6,%7}, {%8,%9}, {%0,%1,%2,%3};\n"
        : "+f"(d[0]), "+f"(d[1]), "+f"(d[2]), "+f"(d[3])
        : "r"(a[0]), "r"(a[1]), "r"(a[2]), "r"(a[3]), "r"(b0), "r"(b1));
}

__device__ __forceinline__ void ldsm4(uint32_t r[4], uint32_t addr) {
    asm volatile("ldmatrix.sync.aligned.m8n8.x4.shared.b16 {%0,%1,%2,%3}, [%4];"
                 : "=r"(r[0]), "=r"(r[1]), "=r"(r[2]), "=r"(r[3]) : "r"(addr));
}
__device__ __forceinline__ void ldsm4t(uint32_t r[4], uint32_t addr) {
    asm volatile("ldmatrix.sync.aligned.m8n8.x4.trans.shared.b16 {%0,%1,%2,%3}, [%4];"
                 : "=r"(r[0]), "=r"(r[1]), "=r"(r[2]), "=r"(r[3]) : "r"(addr));
}

// ===========================================================================
// Mask bit-pack: int32[H*L*L] -> u32 bits (ballot). Standalone, 16K warps to
// saturate DRAM (fusing into the GEMM grid cut MLP 8x and cost 400us: R14).
// ===========================================================================
__global__ __launch_bounds__(256)
void maskpack_kernel(const int* __restrict__ mask, uint32_t* __restrict__ mp)
{
    const int lane = threadIdx.x & 31;
    const int wgid = (blockIdx.x * blockDim.x + threadIdx.x) >> 5;
    const int nw   = (gridDim.x * blockDim.x) >> 5;
    for (int w = wgid; w < MP_WORDS; w += nw) {
        int v = mask[(size_t)w * 32 + lane];
        uint32_t bits = __ballot_sync(0xffffffffu, v != 0);
        if (lane == 0) mp[w] = bits;
    }
}

// ===========================================================================
// bf16 3xsplit NT GEMM, CTA tile 128x128 (3x less STS, 25% less LDSM per
// FLOP vs 64x128 — GEMM is L1-pipe-bound per R16 profile). Warp 64x32,
// 8 warps (2m x 4n), BK=32, double-buffered 2x40KB smem, occupancy 1.
// MODE 0: fp32 C.  MODE 1: fp16 C (Ch).  MODE 2: fp16 hi/lo C (Ch, Cl).
// ===========================================================================
#define G_OFF_AH 0
#define G_OFF_AL 10240
#define G_OFF_BH 20480
#define G_OFF_BL 30720
#define G_BUF    40960
#define GEMM_SMEM (2 * G_BUF)    // 81920

template<int MODE>
__device__ __forceinline__ void gemm_body(const float* __restrict__ A,
                                          const float* __restrict__ B,
                                          float* __restrict__ C,
                                          __half* __restrict__ Ch,
                                          __half* __restrict__ Cl,
                                          int bm, int bn)
{
    extern __shared__ char gsm[];
    const uint32_t sb = smem_u32(gsm);

    const int tid  = threadIdx.x;
    const int lane = tid & 31;
    const int wid  = tid >> 5;
    const int g    = lane >> 2;
    const int t4   = lane & 3;
    const int wm   = (wid & 1) * 64;      // warp m offset (64-row tile)
    const int wn   = (wid >> 1) * 32;     // warp n offset (32-col tile)

    // loaders: both A and B are 128 rows x 32 cols; 2 thr/row, 16 cols each
    const int lr = tid >> 1, lw = tid & 1;
    const float* ap = A + (size_t)(bm + lr) * EMB + lw * 16;
    const float* bp = B + (size_t)(bn + lr) * EMB + lw * 16;

    // ldmatrix base addresses (buffer offset added at use)
    const int arow = lane & 15, akoff = (lane >> 4) * 16;
    const int brow = (lane & 7) + ((lane >> 4) << 3);
    const int bkoff = ((lane >> 3) & 1) * 16;
    uint32_t aAh[4], aAl[4], aBh[2], aBl[2];
    #pragma unroll
    for (int mi = 0; mi < 4; ++mi) {
        aAh[mi] = sb + G_OFF_AH + (wm + 16 * mi + arow) * 80 + akoff;
        aAl[mi] = sb + G_OFF_AL + (wm + 16 * mi + arow) * 80 + akoff;
    }
    #pragma unroll
    for (int p = 0; p < 2; ++p) {
        aBh[p] = sb + G_OFF_BH + (wn + 16 * p + brow) * 80 + bkoff;
        aBl[p] = sb + G_OFF_BL + (wn + 16 * p + brow) * 80 + bkoff;
    }

    // STS byte offset within a plane (uint4 at +0 and +16)
    const int sR = lr * 80 + lw * 32;

    float d[4][4][4];
    #pragma unroll
    for (int i = 0; i < 4; ++i)
        #pragma unroll
        for (int j = 0; j < 4; ++j)
            #pragma unroll
            for (int r = 0; r < 4; ++r) d[i][j][r] = 0.f;

    float4 pa0 = *(const float4*)(ap);
    float4 pa1 = *(const float4*)(ap + 4);
    float4 pa2 = *(const float4*)(ap + 8);
    float4 pa3 = *(const float4*)(ap + 12);
    float4 pb0 = *(const float4*)(bp);
    float4 pb1 = *(const float4*)(bp + 4);
    float4 pb2 = *(const float4*)(bp + 8);
    float4 pb3 = *(const float4*)(bp + 12);

    // split one 16-float row segment (4 float4 regs) into hi/lo planes
    #define GSPLIT(P0, P1, P2, P3, HOFF, LOFF, BASE) do {                        \
        uint32_t h0 = cvt2bf(P0.x, P0.y), h1 = cvt2bf(P0.z, P0.w);               \
        uint32_t h2 = cvt2bf(P1.x, P1.y), h3 = cvt2bf(P1.z, P1.w);               \
        uint32_t h4 = cvt2bf(P2.x, P2.y), h5 = cvt2bf(P2.z, P2.w);               \
        uint32_t h6 = cvt2bf(P3.x, P3.y), h7 = cvt2bf(P3.z, P3.w);               \
        uint32_t l0 = cvt2bf(P0.x - bf_lowf(h0), P0.y - bf_highf(h0));           \
        uint32_t l1 = cvt2bf(P0.z - bf_lowf(h1), P0.w - bf_highf(h1));           \
        uint32_t l2 = cvt2bf(P1.x - bf_lowf(h2), P1.y - bf_highf(h2));           \
        uint32_t l3 = cvt2bf(P1.z - bf_lowf(h3), P1.w - bf_highf(h3));           \
        uint32_t l4 = cvt2bf(P2.x - bf_lowf(h4), P2.y - bf_highf(h4));           \
        uint32_t l5 = cvt2bf(P2.z - bf_lowf(h5), P2.w - bf_highf(h5));           \
        uint32_t l6 = cvt2bf(P3.x - bf_lowf(h6), P3.y - bf_highf(h6));           \
        uint32_t l7 = cvt2bf(P3.z - bf_lowf(h7), P3.w - bf_highf(h7));           \
        *(uint4*)((BASE) + (HOFF) + sR)      = make_uint4(h0, h1, h2, h3);       \
        *(uint4*)((BASE) + (HOFF) + sR + 16) = make_uint4(h4, h5, h6, h7);       \
        *(uint4*)((BASE) + (LOFF) + sR)      = make_uint4(l0, l1, l2, l3);       \
        *(uint4*)((BASE) + (LOFF) + sR + 16) = make_uint4(l4, l5, l6, l7);       \
    } while (0)

    #define GSTAGE(BUF) do {                                                     \
        char* base = gsm + (BUF) * G_BUF;                                        \
        GSPLIT(pa0, pa1, pa2, pa3, G_OFF_AH, G_OFF_AL, base);                    \
        GSPLIT(pb0, pb1, pb2, pb3, G_OFF_BH, G_OFF_BL, base);                    \
    } while (0)

    GSTAGE(0);
    __syncthreads();

    #pragma unroll 1
    for (int c = 0; c < EMB / 32; ++c) {
        const int b = c & 1;
        const uint32_t boff = b * G_BUF;

        // prefetch next chunk (hides under the 96 MMAs below)
        if (c + 1 < EMB / 32) {
            pa0 = *(const float4*)(ap + (c + 1) * 32);
            pa1 = *(const float4*)(ap + (c + 1) * 32 + 4);
            pa2 = *(const float4*)(ap + (c + 1) * 32 + 8);
            pa3 = *(const float4*)(ap + (c + 1) * 32 + 12);
            pb0 = *(const float4*)(bp + (c + 1) * 32);
            pb1 = *(const float4*)(bp + (c + 1) * 32 + 4);
            pb2 = *(const float4*)(bp + (c + 1) * 32 + 8);
            pb3 = *(const float4*)(bp + (c + 1) * 32 + 12);
        }

        // compute from buffer b
        #pragma unroll
        for (int kk = 0; kk < 2; ++kk) {
            uint32_t fbh[2][4], fbl[2][4];
            #pragma unroll
            for (int p = 0; p < 2; ++p) {
                ldsm4(fbh[p], aBh[p] + boff + kk * 32);
                ldsm4(fbl[p], aBl[p] + boff + kk * 32);
            }
            #pragma unroll
            for (int mi = 0; mi < 4; ++mi) {
                uint32_t fah[4], fal[4];
                ldsm4(fah, aAh[mi] + boff + kk * 32);
                ldsm4(fal, aAl[mi] + boff + kk * 32);
                #pragma unroll
                for (int ni = 0; ni < 4; ++ni) {
                    const int p = ni >> 1, q = (ni & 1) * 2;
                    uint32_t b0h = fbh[p][q], b1h = fbh[p][q + 1];
                    uint32_t b0l = fbl[p][q], b1l = fbl[p][q + 1];
                    mma_bf16(d[mi][ni], fah, b0h, b1h);
                    mma_bf16(d[mi][ni], fah, b0l, b1l);
                    mma_bf16(d[mi][ni], fal, b0h, b1h);
                }
            }
        }

        // stage next chunk into the other buffer
        if (c + 1 < EMB / 32) GSTAGE(b ^ 1);
        __syncthreads();
    }

    #pragma unroll
    for (int mi = 0; mi < 4; ++mi) {
        int m = bm + wm + mi * 16 + g;
        #pragma unroll
        for (int ni = 0; ni < 4; ++ni) {
            int n = bn + wn + ni * 8 + 2 * t4;
            if (MODE == 0) {
                *(float2*)(C + (size_t)m * EMB + n) =
                    make_float2(d[mi][ni][0], d[mi][ni][1]);
                *(float2*)(C + (size_t)(m + 8) * EMB + n) =
                    make_float2(d[mi][ni][2], d[mi][ni][3]);
            } else if (MODE == 1) {
                *(uint32_t*)(Ch + (size_t)m * EMB + n) =
                    cvt2h(d[mi][ni][0], d[mi][ni][1]);
                *(uint32_t*)(Ch + (size_t)(m + 8) * EMB + n) =
                    cvt2h(d[mi][ni][2], d[mi][ni][3]);
            } else {
                uint32_t vh0 = cvt2h(d[mi][ni][0], d[mi][ni][1]);
                uint32_t vl0 = cvt2h(d[mi][ni][0] - h_lowf(vh0),
                                     d[mi][ni][1] - h_highf(vh0));
                uint32_t vh1 = cvt2h(d[mi][ni][2], d[mi][ni][3]);
                uint32_t vl1 = cvt2h(d[mi][ni][2] - h_lowf(vh1),
                                     d[mi][ni][3] - h_highf(vh1));
                *(uint32_t*)(Ch + (size_t)m * EMB + n)       = vh0;
                *(uint32_t*)(Cl + (size_t)m * EMB + n)       = vl0;
                *(uint32_t*)(Ch + (size_t)(m + 8) * EMB + n) = vh1;
                *(uint32_t*)(Cl + (size_t)(m + 8) * EMB + n) = vl1;
            }
        }
    }
    #undef GSTAGE
    #undef GSPLIT
}

// fused QKV projection: z==0 Q (fp32), z==1 K (fp16), z==2 V (fp16 hi/lo)
__global__ __launch_bounds__(256, 1)
void gemm_qkv_kernel(const float* __restrict__ q, const float* __restrict__ k,
                     const float* __restrict__ v, const float* __restrict__ Wq,
                     const float* __restrict__ Wk, const float* __restrict__ Wv,
                     float* __restrict__ Qo, __half* __restrict__ Kh,
                     __half* __restrict__ Vh, __half* __restrict__ Vl)
{
    const int z = blockIdx.z;
    const int bm = blockIdx.y * 128, bn = blockIdx.x * 128;
    if (z == 0)      gemm_body<0>(q, Wq, Qo, nullptr, nullptr, bm, bn);
    else if (z == 1) gemm_body<1>(k, Wk, nullptr, Kh, nullptr, bm, bn);
    else             gemm_body<2>(v, Wv, nullptr, Vh, Vl, bm, bn);
}

__global__ __launch_bounds__(256, 1)
void gemm_mma_kernel(const float* __restrict__ A, const float* __restrict__ B,
                     float* __restrict__ C)
{
    gemm_body<0>(A, B, C, nullptr, nullptr, blockIdx.y * 128, blockIdx.x * 128);
}

// ===========================================================================
// Tensor-core flash attention v8 (unchanged from R15/R16): K/V pre-converted
// fp16, raw uint4 staging, Q fp16 2-split, K single, P single, V 2-split.
// ===========================================================================
#define KROWB  144
#define PLANE  (64 * KROWB)          // 9216
#define KBUFB  PLANE                 // K: hi only
#define VBUFB  (2 * PLANE)           // V: hi+lo
#define OFF_V  (2 * KBUFB)           // 18432
#define ATTN_SMEM (2 * KBUFB + 2 * VBUFB)   // 55296

__global__ __launch_bounds__(256, 2)
void attn_mma_kernel(const float* __restrict__ Q, const __half* __restrict__ Kh,
                     const __half* __restrict__ Vh, const __half* __restrict__ Vl,
                     const uint32_t* __restrict__ Mp, float* __restrict__ O)
{
    extern __shared__ char smem[];
    const uint32_t sbase = smem_u32(smem);

    const int tid  = threadIdx.x;
    const int lane = tid & 31;
    const int wid  = tid >> 5;
    const int g    = lane >> 2;
    const int t4   = lane & 3;
    const int h    = blockIdx.y;
    const int qb   = blockIdx.x;
    const int hb   = h * HD;
    const int row0 = qb * 128 + wid * 16;

    // ---- Q fragments: fp16 hi/lo, resident in regs ----
    uint32_t qfh[4][4], qfl[4][4];
    #pragma unroll
    for (int s = 0; s < 4; ++s) {
        const float* qr0 = Q + (size_t)(row0 + g)     * EMB + hb + 16 * s + 2 * t4;
        const float* qr1 = Q + (size_t)(row0 + g + 8) * EMB + hb + 16 * s + 2 * t4;
        float x0 = qr0[0] * 0.125f, x1 = qr0[1] * 0.125f;
        float y0 = qr1[0] * 0.125f, y1 = qr1[1] * 0.125f;
        float z0 = qr0[8] * 0.125f, z1 = qr0[9] * 0.125f;
        float w0 = qr1[8] * 0.125f, w1 = qr1[9] * 0.125f;
        qfh[s][0] = cvt2h(x0, x1);
        qfl[s][0] = cvt2h(x0 - h_lowf(qfh[s][0]), x1 - h_highf(qfh[s][0]));
        qfh[s][1] = cvt2h(y0, y1);
        qfl[s][1] = cvt2h(y0 - h_lowf(qfh[s][1]), y1 - h_highf(qfh[s][1]));
        qfh[s][2] = cvt2h(z0, z1);
        qfl[s][2] = cvt2h(z0 - h_lowf(qfh[s][2]), z1 - h_highf(qfh[s][2]));
        qfh[s][3] = cvt2h(w0, w1);
        qfl[s][3] = cvt2h(w0 - h_lowf(qfh[s][3]), w1 - h_highf(qfh[s][3]));
    }

    float o[8][4];
    #pragma unroll
    for (int ni = 0; ni < 8; ++ni)
        #pragma unroll
        for (int r = 0; r < 4; ++r) o[ni][r] = 0.f;
    float m0 = -1.0e30f, m1 = -1.0e30f;
    float l0 = 0.f, l1 = 0.f;

    // staging coordinates: thread stages key row `key`, 16-dim segment qq
    const int key = tid >> 2;
    const int qq  = tid & 3;
    const __half* kb = Kh + (size_t)key * EMB + hb + qq * 16;
    const __half* vh = Vh + (size_t)key * EMB + hb + qq * 16;
    const __half* vl = Vl + (size_t)key * EMB + hb + qq * 16;

    // ldmatrix read addresses
    const int brow  = (lane & 7) + ((lane >> 4) << 3);
    const int bkoff = ((lane >> 3) & 1) * 16;
    const uint32_t kaddr0 = sbase + brow * KROWB + bkoff;
    const uint32_t vaddr0 = sbase + OFF_V + (lane & 15) * KROWB + ((lane >> 4) << 3) * 2;

    const int rbase = wid * 16 + g;
    const uint32_t* mp0 = Mp + ((size_t)h * Lq + qb * 128 + rbase) * (Lq / 32);
    const uint32_t* mp1 = mp0 + 8 * (Lq / 32);

    // raw copies: K one plane, V two planes
    #define STAGE_TILE(T, BUF) do {                                              \
        const __half* ks = kb + (size_t)(T) * 64 * EMB;                          \
        const __half* vsh = vh + (size_t)(T) * 64 * EMB;                         \
        const __half* vsl = vl + (size_t)(T) * 64 * EMB;                         \
        uint4 k0 = *(const uint4*)(ks);                                          \
        uint4 k1 = *(const uint4*)(ks + 8);                                      \
        uint4 vh0 = *(const uint4*)(vsh);                                        \
        uint4 vh1 = *(const uint4*)(vsh + 8);                                    \
        uint4 vl0 = *(const uint4*)(vsl);                                        \
        uint4 vl1 = *(const uint4*)(vsl + 8);                                    \
        char* kd = smem + (BUF) * KBUFB + key * KROWB + qq * 32;                 \
        char* vd = smem + OFF_V + (BUF) * VBUFB + key * KROWB + qq * 32;         \
        *(uint4*)(kd)              = k0;                                         \
        *(uint4*)(kd + 16)         = k1;                                         \
        *(uint4*)(vd)              = vh0;                                        \
        *(uint4*)(vd + 16)         = vh1;                                        \
        *(uint4*)(vd + PLANE)      = vl0;                                        \
        *(uint4*)(vd + PLANE + 16) = vl1;                                        \
    } while (0)

    STAGE_TILE(0, 0);
    __syncthreads();

    #pragma unroll 1
    for (int kt = 0; kt < NT; ++kt) {
        const int b = kt & 1;

        uint32_t cm0 = mp0[kt * 2],     cm1 = mp0[kt * 2 + 1];
        uint32_t cm2 = mp1[kt * 2],     cm3 = mp1[kt * 2 + 1];

        if (kt + 1 < NT) STAGE_TILE(kt + 1, b ^ 1);

        // ================= S = Q K^T (Q fp16 2-split x K fp16 single) ======
        float s[8][4];
        #pragma unroll
        for (int ni = 0; ni < 8; ++ni)
            #pragma unroll
            for (int r = 0; r < 4; ++r) s[ni][r] = 0.f;

        const uint32_t ka = kaddr0 + b * KBUFB;
        #pragma unroll
        for (int sstep = 0; sstep < 4; ++sstep) {
            #pragma unroll
            for (int p = 0; p < 4; ++p) {
                uint32_t fh[4];
                ldsm4(fh, ka + p * 16 * KROWB + sstep * 32);
                #pragma unroll
                for (int q = 0; q < 2; ++q) {
                    const int ni = 2 * p + q;
                    mma_f16(s[ni], qfh[sstep], fh[2 * q], fh[2 * q + 1]);
                    mma_f16(s[ni], qfl[sstep], fh[2 * q], fh[2 * q + 1]);
                }
            }
        }

        // ================= masked online softmax ===========================
        float tm0 = -1.0e30f, tm1 = -1.0e30f;
        #pragma unroll
        for (int ni = 0; ni < 8; ++ni) {
            uint32_t wr0 = (ni < 4) ? cm0 : cm1;
            uint32_t wr1 = (ni < 4) ? cm2 : cm3;
            int b2 = 8 * (ni & 3) + 2 * t4;
            tm0 = fmaxf(tm0, ((wr0 >> b2) & 1u)       ? -1.0e30f : s[ni][0]);
            tm0 = fmaxf(tm0, ((wr0 >> (b2 + 1)) & 1u) ? -1.0e30f : s[ni][1]);
            tm1 = fmaxf(tm1, ((wr1 >> b2) & 1u)       ? -1.0e30f : s[ni][2]);
            tm1 = fmaxf(tm1, ((wr1 >> (b2 + 1)) & 1u) ? -1.0e30f : s[ni][3]);
        }
        tm0 = fmaxf(tm0, __shfl_xor_sync(0xffffffffu, tm0, 1));
        tm0 = fmaxf(tm0, __shfl_xor_sync(0xffffffffu, tm0, 2));
        tm1 = fmaxf(tm1, __shfl_xor_sync(0xffffffffu, tm1, 1));
        tm1 = fmaxf(tm1, __shfl_xor_sync(0xffffffffu, tm1, 2));

        float mn0 = fmaxf(m0, tm0), mn1 = fmaxf(m1, tm1);
        float c0 = __expf(m0 - mn0), c1 = __expf(m1 - mn1);
        m0 = mn0; m1 = mn1;

        float rs0 = 0.f, rs1 = 0.f;
        #pragma unroll
        for (int ni = 0; ni < 8; ++ni) {
            uint32_t wr0 = (ni < 4) ? cm0 : cm1;
            uint32_t wr1 = (ni < 4) ? cm2 : cm3;
            int b2 = 8 * (ni & 3) + 2 * t4;
            float p0 = ((wr0 >> b2) & 1u)       ? 0.f : __expf(s[ni][0] - mn0);
            float p1 = ((wr0 >> (b2 + 1)) & 1u) ? 0.f : __expf(s[ni][1] - mn0);
            float p2 = ((wr1 >> b2) & 1u)       ? 0.f : __expf(s[ni][2] - mn1);
            float p3 = ((wr1 >> (b2 + 1)) & 1u) ? 0.f : __expf(s[ni][3] - mn1);
            s[ni][0] = p0; s[ni][1] = p1; s[ni][2] = p2; s[ni][3] = p3;
            rs0 += p0 + p1; rs1 += p2 + p3;
        }
        rs0 += __shfl_xor_sync(0xffffffffu, rs0, 1);
        rs0 += __shfl_xor_sync(0xffffffffu, rs0, 2);
        rs1 += __shfl_xor_sync(0xffffffffu, rs1, 1);
        rs1 += __shfl_xor_sync(0xffffffffu, rs1, 2);
        l0 = l0 * c0 + rs0;
        l1 = l1 * c1 + rs1;

        #pragma unroll
        for (int ni = 0; ni < 8; ++ni) {
            o[ni][0] *= c0; o[ni][1] *= c0;
            o[ni][2] *= c1; o[ni][3] *= c1;
        }

        // ================= O += P V (P single fp16, V fp16 2-split) ========
        {
            const uint32_t va = vaddr0 + b * VBUFB;
            #pragma unroll
            for (int st = 0; st < 4; ++st) {
                uint32_t ah[4];
                ah[0] = cvt2h(s[2 * st][0],     s[2 * st][1]);
                ah[1] = cvt2h(s[2 * st][2],     s[2 * st][3]);
                ah[2] = cvt2h(s[2 * st + 1][0], s[2 * st + 1][1]);
                ah[3] = cvt2h(s[2 * st + 1][2], s[2 * st + 1][3]);
                #pragma unroll
                for (int np = 0; np < 4; ++np) {
                    uint32_t bh[4], bl[4];
                    ldsm4t(bh, va + st * (16 * KROWB) + np * 32);
                    ldsm4t(bl, va + st * (16 * KROWB) + np * 32 + PLANE);
                    mma_f16(o[2 * np],     ah, bh[0], bh[1]);
                    mma_f16(o[2 * np],     ah, bl[0], bl[1]);
                    mma_f16(o[2 * np + 1], ah, bh[2], bh[3]);
                    mma_f16(o[2 * np + 1], ah, bl[2], bl[3]);
                }
            }
        }

        __syncthreads();
    }

    // ================= epilogue =================
    float inv0 = (l0 > 0.f) ? (1.f / l0) : 0.f;
    float inv1 = (l1 > 0.f) ? (1.f / l1) : 0.f;
    #pragma unroll
    for (int ni = 0; ni < 8; ++ni) {
        int col = hb + 8 * ni + 2 * t4;
        *(float2*)(O + (size_t)(row0 + g)     * EMB + col) =
            make_float2(o[ni][0] * inv0, o[ni][1] * inv0);
        *(float2*)(O + (size_t)(row0 + g + 8) * EMB + col) =
            make_float2(o[ni][2] * inv1, o[ni][3] * inv1);
    }
}

// ---------------------------------------------------------------------------
extern "C" void kernel_launch(void* const* d_in, const int* in_sizes, int n_in,
                              void* d_out, int out_size)
{
    const float* q    = (const float*)d_in[0];
    const float* k    = (const float*)d_in[1];
    const float* v    = (const float*)d_in[2];
    const int*   mask = (const int*)d_in[3];
    const float* Wq   = (const float*)d_in[4];
    const float* Wk   = (const float*)d_in[5];
    const float* Wv   = (const float*)d_in[6];
    const float* Wo   = (const float*)d_in[7];
    float*       out  = (float*)d_out;

    float *gQ, *gA;
    __half *gKh, *gVh, *gVl;
    uint32_t* gMp;
    cudaGetSymbolAddress((void**)&gQ,  g_Q);
    cudaGetSymbolAddress((void**)&gKh, g_Kh);
    cudaGetSymbolAddress((void**)&gVh, g_Vh);
    cudaGetSymbolAddress((void**)&gVl, g_Vl);
    cudaGetSymbolAddress((void**)&gA,  g_A);
    cudaGetSymbolAddress((void**)&gMp, g_Mp);

    cudaFuncSetAttribute(attn_mma_kernel,
                         cudaFuncAttributeMaxDynamicSharedMemorySize, ATTN_SMEM);
    cudaFuncSetAttribute(gemm_qkv_kernel,
                         cudaFuncAttributeMaxDynamicSharedMemorySize, GEMM_SMEM);
    cudaFuncSetAttribute(gemm_mma_kernel,
                         cudaFuncAttributeMaxDynamicSharedMemorySize, GEMM_SMEM);

    maskpack_kernel<<<2048, 256>>>(mask, gMp);

    dim3 qkvgrid(EMB / 128, Lq / 128, 3);  // (8, 16, 3) = 384 CTAs
    gemm_qkv_kernel<<<qkvgrid, 256, GEMM_SMEM>>>(q, k, v, Wq, Wk, Wv,
                                                 gQ, gKh, gVh, gVl);

    dim3 agrid(Lq / 128, NHEAD);           // (16, 16)
    attn_mma_kernel<<<agrid, 256, ATTN_SMEM>>>(gQ, gKh, gVh, gVl, gMp, gA);

    dim3 ggrid(EMB / 128, Lq / 128);       // (8, 16) = 128 CTAs, single wave
    gemm_mma_kernel<<<ggrid, 256, GEMM_SMEM>>>(gA, Wo, out);
}